// round 3
// baseline (speedup 1.0000x reference)
#include <cuda_runtime.h>
#include <math.h>

static constexpr int B_ = 2, N_ = 4096, C_ = 128, K_ = 16, P_ = 43, CLS_ = 16, F_ = 512;
static constexpr int M_ = B_ * N_;
static constexpr int PC_ = P_ * C_;          // 5504
static constexpr float R2_ = 0.01f;          // RADIUS^2
static constexpr float INV_SIG_ = 10.0f;     // 1/RADIUS

// ---------------- static device scratch (no allocations) ----------------
__device__ float g_xyz[M_ * 3];
__device__ float g_sq[M_];
__device__ int   g_nbr[M_ * K_];
__device__ float g_kpts[P_ * 3];
__device__ float g_f[M_ * C_];
__device__ float g_x0[M_ * C_];
__device__ float g_fk[(size_t)M_ * PC_];     // 180 MB
__device__ float g_pts[M_ * C_];
__device__ float g_xn[M_ * C_];
__device__ float g_mk[M_ * C_];
__device__ float g_mv[M_ * C_];
__device__ float g_mr[M_ * C_];
__device__ float g_kk[M_ * C_];
__device__ float g_vv[M_ * C_];
__device__ float g_rr[M_ * C_];
__device__ float g_kT[M_ * C_];
__device__ float g_vT[M_ * C_];
__device__ float g_wkv[M_ * C_];
__device__ float g_ffn[M_ * F_];
__device__ float g_p1[32 * C_];
__device__ float g_p2[32 * C_];
__device__ float g_bnA[C_];
__device__ float g_bnB[C_];

// ---------------- kernel points (fp64, matches numpy fibonacci sphere) ----------------
__global__ void k_init_kpts() {
    int t = threadIdx.x;
    if (t >= P_) return;
    double x = 0.0, y = 0.0, z = 0.0;
    if (t > 0) {
        int mc = (t <= 14) ? 14 : 28;
        double scale = (t <= 14) ? 0.05 : 0.1;
        int i0 = (t <= 14) ? (t - 1) : (t - 15);
        double i = i0 + 0.5;
        double phi = acos(1.0 - 2.0 * i / (double)mc);
        double theta = 3.141592653589793 * (1.0 + sqrt(5.0)) * i;
        x = cos(theta) * sin(phi) * scale;
        y = sin(theta) * sin(phi) * scale;
        z = cos(phi) * scale;
    }
    g_kpts[t * 3 + 0] = (float)x;
    g_kpts[t * 3 + 1] = (float)y;
    g_kpts[t * 3 + 2] = (float)z;
}

// ---------------- prep ----------------
__global__ void k_prep_xyz(const float* __restrict__ p) {
    int m = blockIdx.x * blockDim.x + threadIdx.x;
    if (m >= M_) return;
    int b = m / N_, n = m - b * N_;
    float x = p[((size_t)b * 3 + 0) * N_ + n];
    float y = p[((size_t)b * 3 + 1) * N_ + n];
    float z = p[((size_t)b * 3 + 2) * N_ + n];
    g_xyz[m * 3 + 0] = x; g_xyz[m * 3 + 1] = y; g_xyz[m * 3 + 2] = z;
    g_sq[m] = fmaf(x, x, fmaf(y, y, z * z));
}

__global__ void k_prep_feat(const float* __restrict__ x) {
    int i = blockIdx.x * blockDim.x + threadIdx.x;
    if (i >= M_ * C_) return;
    int m = i / C_, c = i - m * C_;
    int b = m / N_, n = m - b * N_;
    float v = x[((size_t)b * C_ + c) * N_ + n];
    g_f[i] = v;
    g_x0[i] = v;
}

// ---------------- radius-limited 16-NN (stable ties like lax.top_k) ----------------
__global__ void __launch_bounds__(256) k_knn() {
    int m = blockIdx.x * 256 + threadIdx.x;   // blocks never straddle batches
    int b = m / N_;
    float qx = g_xyz[m * 3], qy = g_xyz[m * 3 + 1], qz = g_xyz[m * 3 + 2];
    float qsq = g_sq[m];
    float bd[K_]; int bi[K_];
#pragma unroll
    for (int k = 0; k < K_; k++) { bd[k] = 3.4e38f; bi[k] = 0; }
    float worst = 3.4e38f;
    __shared__ float sx[512], sy[512], sz[512], ss[512];
    int base = b * N_;
    for (int t0 = 0; t0 < N_; t0 += 512) {
        __syncthreads();
        for (int j = threadIdx.x; j < 512; j += 256) {
            int g = base + t0 + j;
            sx[j] = g_xyz[g * 3]; sy[j] = g_xyz[g * 3 + 1]; sz[j] = g_xyz[g * 3 + 2];
            ss[j] = g_sq[g];
        }
        __syncthreads();
        for (int j = 0; j < 512; j++) {
            float dot = fmaf(qx, sx[j], fmaf(qy, sy[j], qz * sz[j]));
            float d2 = qsq + ss[j] - 2.0f * dot;
            // only in-radius candidates can survive into the final idx
            // (out-of-radius entries are replaced by idx[...,:1] = self, d2(self)=0)
            if (d2 <= R2_ && d2 < worst) {
                int pos = K_ - 1;
                for (; pos > 0 && bd[pos - 1] > d2; pos--) {
                    bd[pos] = bd[pos - 1]; bi[pos] = bi[pos - 1];
                }
                bd[pos] = d2; bi[pos] = t0 + j;
                worst = bd[K_ - 1];
            }
        }
    }
    int nearest = bi[0];
#pragma unroll
    for (int k = 0; k < K_; k++) {
        int sel = (bd[k] <= R2_) ? bi[k] : nearest;
        g_nbr[m * K_ + k] = base + sel;
    }
}

// ---------------- build fk[m, p*C+c] = sum_k infl[m,k,p] * f[nbr(m,k), c] ----------------
__global__ void __launch_bounds__(128) k_build_fk(const float* __restrict__ fin) {
    int m = blockIdx.x;
    int tid = threadIdx.x;
    __shared__ float infl[K_][P_ + 5];
    __shared__ float nx[K_], ny[K_], nz[K_];
    __shared__ int nidx[K_];
    float cx = g_xyz[m * 3], cy = g_xyz[m * 3 + 1], cz = g_xyz[m * 3 + 2];
    if (tid < K_) {
        int nb = g_nbr[m * K_ + tid];
        nidx[tid] = nb;
        nx[tid] = g_xyz[nb * 3]; ny[tid] = g_xyz[nb * 3 + 1]; nz[tid] = g_xyz[nb * 3 + 2];
    }
    __syncthreads();
    for (int e = tid; e < K_ * P_; e += 128) {
        int k = e / P_, pp = e - k * P_;
        float rx = nx[k] - cx, ry = ny[k] - cy, rz = nz[k] - cz;
        float dx = rx - g_kpts[pp * 3], dy = ry - g_kpts[pp * 3 + 1], dz = rz - g_kpts[pp * 3 + 2];
        float d = sqrtf(fmaf(dx, dx, fmaf(dy, dy, dz * dz)) + 1e-12f);
        infl[k][pp] = fmaxf(0.0f, 1.0f - d * INV_SIG_);
    }
    __syncthreads();
    float Fv[K_];
#pragma unroll
    for (int k = 0; k < K_; k++) Fv[k] = fin[(size_t)nidx[k] * C_ + tid];
    float* dst = g_fk + (size_t)m * PC_ + tid;
#pragma unroll 1
    for (int pp = 0; pp < P_; pp++) {
        float acc = 0.f;
#pragma unroll
        for (int k = 0; k < K_; k++) acc = fmaf(infl[k][pp], Fv[k], acc);
        dst[pp * C_] = acc;
    }
}

// ---------------- generic fp32 GEMM: out = ep(A@B) * Mul + Res ----------------
// BM=BN=64, BK=16, 256 threads, 4x4 micro-tiles. All dims multiples of tile sizes.
// ep: 0=none, 1=sigmoid, 2=relu^2
__global__ void __launch_bounds__(256) k_gemm(
    const float* __restrict__ A, const float* __restrict__ Bm, float* __restrict__ Cm,
    const float* __restrict__ Res, const float* __restrict__ Mul,
    int Md, int Nd, int Kd, int ep)
{
    __shared__ float As[16][68];
    __shared__ float Bs[16][68];
    int bm = blockIdx.x * 64;
    int bn = blockIdx.y * 64;
    int tid = threadIdx.x;
    int ar = tid >> 2, ak = (tid & 3) << 2;      // A tile: 64 rows x 16 k
    int bk = tid >> 4, bc = (tid & 15) << 2;     // B tile: 16 k x 64 cols
    int tx = (tid & 15) << 2, ty = (tid >> 4) << 2;
    float acc[4][4];
#pragma unroll
    for (int i = 0; i < 4; i++)
#pragma unroll
        for (int j = 0; j < 4; j++) acc[i][j] = 0.f;
    const float* Ap = A + (size_t)(bm + ar) * Kd + ak;
    const float* Bp = Bm + (size_t)bk * Nd + bn + bc;
    for (int k0 = 0; k0 < Kd; k0 += 16) {
        float4 a4 = *(const float4*)(Ap + k0);
        float4 b4 = *(const float4*)(Bp + (size_t)k0 * Nd);
        __syncthreads();
        As[ak + 0][ar] = a4.x; As[ak + 1][ar] = a4.y;
        As[ak + 2][ar] = a4.z; As[ak + 3][ar] = a4.w;
        *(float4*)&Bs[bk][bc] = b4;
        __syncthreads();
#pragma unroll
        for (int kk = 0; kk < 16; kk++) {
            float4 av = *(const float4*)&As[kk][ty];
            float4 bv = *(const float4*)&Bs[kk][tx];
            float a0 = av.x, a1 = av.y, a2 = av.z, a3 = av.w;
            float b0 = bv.x, b1 = bv.y, b2 = bv.z, b3 = bv.w;
            acc[0][0] = fmaf(a0, b0, acc[0][0]); acc[0][1] = fmaf(a0, b1, acc[0][1]);
            acc[0][2] = fmaf(a0, b2, acc[0][2]); acc[0][3] = fmaf(a0, b3, acc[0][3]);
            acc[1][0] = fmaf(a1, b0, acc[1][0]); acc[1][1] = fmaf(a1, b1, acc[1][1]);
            acc[1][2] = fmaf(a1, b2, acc[1][2]); acc[1][3] = fmaf(a1, b3, acc[1][3]);
            acc[2][0] = fmaf(a2, b0, acc[2][0]); acc[2][1] = fmaf(a2, b1, acc[2][1]);
            acc[2][2] = fmaf(a2, b2, acc[2][2]); acc[2][3] = fmaf(a2, b3, acc[2][3]);
            acc[3][0] = fmaf(a3, b0, acc[3][0]); acc[3][1] = fmaf(a3, b1, acc[3][1]);
            acc[3][2] = fmaf(a3, b2, acc[3][2]); acc[3][3] = fmaf(a3, b3, acc[3][3]);
        }
    }
#pragma unroll
    for (int i = 0; i < 4; i++) {
        size_t row = (size_t)(bm + ty + i);
#pragma unroll
        for (int j = 0; j < 4; j++) {
            size_t idx = row * Nd + bn + tx + j;
            float v = acc[i][j];
            if (ep == 1) v = 1.0f / (1.0f + __expf(-v));
            else if (ep == 2) { v = fmaxf(v, 0.f); v = v * v; }
            if (Mul) v *= Mul[idx];
            if (Res) v += Res[idx];
            Cm[idx] = v;
        }
    }
}

// ---------------- elementwise add ----------------
__global__ void k_add(const float* __restrict__ a, const float* __restrict__ b,
                      float* __restrict__ o, int n) {
    int i = blockIdx.x * blockDim.x + threadIdx.x;
    if (i < n) o[i] = a[i] + b[i];
}

// ---------------- LayerNorm over last dim (C=128) ----------------
__global__ void __launch_bounds__(128) k_ln(const float* __restrict__ X,
                                            const float* __restrict__ g,
                                            const float* __restrict__ bb,
                                            float* __restrict__ Y) {
    int m = blockIdx.x, c = threadIdx.x;
    float v = X[(size_t)m * C_ + c];
    float s = v, q = v * v;
#pragma unroll
    for (int off = 16; off >= 1; off >>= 1) {
        s += __shfl_xor_sync(0xffffffffu, s, off);
        q += __shfl_xor_sync(0xffffffffu, q, off);
    }
    __shared__ float s1[4], s2[4];
    int w = c >> 5;
    if ((c & 31) == 0) { s1[w] = s; s2[w] = q; }
    __syncthreads();
    s = s1[0] + s1[1] + s1[2] + s1[3];
    q = s2[0] + s2[1] + s2[2] + s2[3];
    float mu = s * (1.0f / C_);
    float var = q * (1.0f / C_) - mu * mu;
    Y[(size_t)m * C_ + c] = (v - mu) * rsqrtf(var + 1e-5f) * g[c] + bb[c];
}

// ---------------- token-shift mix (2 or 3 outputs) ----------------
__global__ void k_mix(const float* __restrict__ xn,
                      const float* __restrict__ mk, const float* __restrict__ mv,
                      const float* __restrict__ mr,
                      float* __restrict__ ok, float* __restrict__ ov, float* __restrict__ orr) {
    int i = blockIdx.x * blockDim.x + threadIdx.x;
    if (i >= M_ * C_) return;
    int m = i >> 7, c = i & 127;
    int n = m & (N_ - 1);
    float xc = xn[i];
    float xp = (n == 0) ? 0.f : xn[i - C_];
    float a = mk[c]; ok[i] = xc * a + xp * (1.f - a);
    if (ov) { a = mv[c]; ov[i] = xc * a + xp * (1.f - a); }
    a = mr[c]; orr[i] = xc * a + xp * (1.f - a);
}

// ---------------- transpose [b,n,c] -> [b,c,n] ----------------
__global__ void k_transpose(const float* __restrict__ in, float* __restrict__ out) {
    __shared__ float t[32][33];
    int b = blockIdx.z;
    int n0 = blockIdx.x * 32, c0 = blockIdx.y * 32;
    int x = threadIdx.x, y = threadIdx.y;   // 32 x 8
    for (int i = y; i < 32; i += 8)
        t[i][x] = in[((size_t)(b * N_ + n0 + i)) * C_ + c0 + x];
    __syncthreads();
    for (int i = y; i < 32; i += 8)
        out[((size_t)(b * C_ + c0 + i)) * N_ + n0 + x] = t[x][i];
}

// ---------------- WKV: warp per (b,c), affine chunked scan ----------------
__global__ void __launch_bounds__(256) k_wkv(
    const float* __restrict__ kT, const float* __restrict__ vT,
    const float* __restrict__ sigr,
    const float* __restrict__ td, const float* __restrict__ tf,
    float* __restrict__ out)
{
    int warp = (blockIdx.x * 256 + threadIdx.x) >> 5;   // 0..255
    int lane = threadIdx.x & 31;
    int b = warp >> 7, c = warp & 127;
    float w = -expf(td[c]);
    float ew = expf(w);
    float etf = expf(tf[c]);
    int n0 = lane * 128;
    const float* kp = kT + ((size_t)(b * C_ + c)) * N_ + n0;
    const float* vp = vT + ((size_t)(b * C_ + c)) * N_ + n0;
    // pass 1: local affine (alpha, betaA, betaB) over this lane's 128 steps
    float A = 0.f, Bv = 0.f;
#pragma unroll 4
    for (int j = 0; j < 128; j++) {
        float ek = __expf(kp[j]);
        A = fmaf(A, ew, ek * vp[j]);
        Bv = fmaf(Bv, ew, ek);
    }
    float al = __expf(128.0f * w);
    // inclusive affine scan over lanes, then shift to exclusive
    float sA = A, sB = Bv, sal = al;
#pragma unroll
    for (int off = 1; off < 32; off <<= 1) {
        float pA = __shfl_up_sync(0xffffffffu, sA, off);
        float pB = __shfl_up_sync(0xffffffffu, sB, off);
        float pal = __shfl_up_sync(0xffffffffu, sal, off);
        if (lane >= off) {
            sA = fmaf(sal, pA, sA);
            sB = fmaf(sal, pB, sB);
            sal = sal * pal;
        }
    }
    float A0 = __shfl_up_sync(0xffffffffu, sA, 1);
    float B0 = __shfl_up_sync(0xffffffffu, sB, 1);
    if (lane == 0) { A0 = 0.f; B0 = 0.f; }
    // pass 2: emit outputs
    A = A0; Bv = B0;
    const float* rp = sigr + ((size_t)(b * N_ + n0)) * C_ + c;
    float* op = out + ((size_t)(b * N_ + n0)) * C_ + c;
#pragma unroll 2
    for (int j = 0; j < 128; j++) {
        float kt = kp[j], vt = vp[j];
        float ek = __expf(kt);
        float ekf = etf * ek;
        float o = (A + ekf * vt) / (Bv + ekf);
        op[(size_t)j * C_] = o * rp[(size_t)j * C_];
        A = fmaf(A, ew, ek * vt);
        Bv = fmaf(Bv, ew, ek);
    }
}

// ---------------- BN stats: deterministic two-stage ----------------
__global__ void __launch_bounds__(128) k_bnpart(const float* __restrict__ pts) {
    int blk = blockIdx.x;    // 32 blocks x 256 rows
    int c = threadIdx.x;
    float s = 0.f, q = 0.f;
    int base = blk * 256;
    for (int r = 0; r < 256; r++) {
        float v = pts[(size_t)(base + r) * C_ + c];
        s += v; q = fmaf(v, v, q);
    }
    g_p1[blk * C_ + c] = s;
    g_p2[blk * C_ + c] = q;
}

__global__ void __launch_bounds__(128) k_bnred(const float* __restrict__ bg,
                                               const float* __restrict__ bb) {
    int c = threadIdx.x;
    float s = 0.f, q = 0.f;
    for (int i = 0; i < 32; i++) { s += g_p1[i * C_ + c]; q += g_p2[i * C_ + c]; }
    float mu = s * (1.0f / M_);
    float var = q * (1.0f / M_) - mu * mu;
    float a = bg[c] * rsqrtf(var + 1e-5f);
    g_bnA[c] = a;
    g_bnB[c] = bb[c] - mu * a;
}

// ---------------- head: label[b,d,n] = conv_w @ relu(BN(pts)) + conv_b ----------------
__global__ void __launch_bounds__(256) k_head(const float* __restrict__ pts,
                                              const float* __restrict__ cw,
                                              const float* __restrict__ cb,
                                              float* __restrict__ label) {
    __shared__ float sw[CLS_ * C_];
    int tid = threadIdx.x;
    for (int i = tid; i < CLS_ * C_; i += 256) sw[i] = cw[i];
    __syncthreads();
    int m = blockIdx.x * 8 + (tid >> 5);
    int lane = tid & 31;
    float yn[4];
#pragma unroll
    for (int j = 0; j < 4; j++) {
        int c = lane + 32 * j;
        float v = fmaf(g_bnA[c], pts[(size_t)m * C_ + c], g_bnB[c]);
        yn[j] = fmaxf(v, 0.f);
    }
    int b = m >> 12, n = m & (N_ - 1);
#pragma unroll 1
    for (int d = 0; d < CLS_; d++) {
        float p = 0.f;
#pragma unroll
        for (int j = 0; j < 4; j++) p = fmaf(yn[j], sw[d * C_ + lane + 32 * j], p);
#pragma unroll
        for (int off = 16; off >= 1; off >>= 1) p += __shfl_xor_sync(0xffffffffu, p, off);
        if (lane == 0)
            label[((size_t)(b * CLS_ + d)) * N_ + n] = p + cb[d];
    }
}

// ---------------- host ----------------
extern "C" void kernel_launch(void* const* d_in, const int* in_sizes, int n_in,
                              void* d_out, int out_size) {
    const float* p        = (const float*)d_in[0];
    const float* x        = (const float*)d_in[1];
    const float* kp1_w    = (const float*)d_in[2];
    const float* kp2_w    = (const float*)d_in[3];
    const float* ln1_g    = (const float*)d_in[4];
    const float* ln1_b    = (const float*)d_in[5];
    const float* tdcy     = (const float*)d_in[6];
    const float* tfst     = (const float*)d_in[7];
    const float* mix_k    = (const float*)d_in[8];
    const float* mix_v    = (const float*)d_in[9];
    const float* mix_r    = (const float*)d_in[10];
    const float* att_wk   = (const float*)d_in[11];
    const float* att_wv   = (const float*)d_in[12];
    const float* att_wr   = (const float*)d_in[13];
    const float* att_wo   = (const float*)d_in[14];
    const float* ln2_g    = (const float*)d_in[15];
    const float* ln2_b    = (const float*)d_in[16];
    const float* cmix_k   = (const float*)d_in[17];
    const float* cmix_r   = (const float*)d_in[18];
    const float* ffn_wk   = (const float*)d_in[19];
    const float* ffn_wv   = (const float*)d_in[20];
    const float* ffn_wr   = (const float*)d_in[21];
    const float* bn_g     = (const float*)d_in[22];
    const float* bn_b     = (const float*)d_in[23];
    const float* conv_w   = (const float*)d_in[24];
    const float* conv_b   = (const float*)d_in[25];

    float* out_y = (float*)d_out;                       // [B, C, N]
    float* out_label = out_y + (size_t)B_ * C_ * N_;    // [B, CLS, N]

    float *gxyz, *gf, *gx0, *gfk, *gpts, *gxn, *gmk, *gmv, *gmr;
    float *gkk, *gvv, *grr, *gkT, *gvT, *gwkv, *gffn;
    cudaGetSymbolAddress((void**)&gxyz, g_xyz);
    cudaGetSymbolAddress((void**)&gf, g_f);
    cudaGetSymbolAddress((void**)&gx0, g_x0);
    cudaGetSymbolAddress((void**)&gfk, g_fk);
    cudaGetSymbolAddress((void**)&gpts, g_pts);
    cudaGetSymbolAddress((void**)&gxn, g_xn);
    cudaGetSymbolAddress((void**)&gmk, g_mk);
    cudaGetSymbolAddress((void**)&gmv, g_mv);
    cudaGetSymbolAddress((void**)&gmr, g_mr);
    cudaGetSymbolAddress((void**)&gkk, g_kk);
    cudaGetSymbolAddress((void**)&gvv, g_vv);
    cudaGetSymbolAddress((void**)&grr, g_rr);
    cudaGetSymbolAddress((void**)&gkT, g_kT);
    cudaGetSymbolAddress((void**)&gvT, g_vT);
    cudaGetSymbolAddress((void**)&gwkv, g_wkv);
    cudaGetSymbolAddress((void**)&gffn, g_ffn);

    dim3 tb(32, 8);
    dim3 tgrid(N_ / 32, C_ / 32, B_);

    k_init_kpts<<<1, 64>>>();
    k_prep_xyz<<<(M_ + 255) / 256, 256>>>(p);
    k_prep_feat<<<(M_ * C_ + 255) / 256, 256>>>(x);
    k_knn<<<M_ / 256, 256>>>();

    // KPConv 1
    k_build_fk<<<M_, 128>>>(gf);
    k_gemm<<<dim3(M_ / 64, C_ / 64), 256>>>(gfk, kp1_w, gf, gf, nullptr, M_, C_, PC_, 0);
    // KPConv 2
    k_build_fk<<<M_, 128>>>(gf);
    k_gemm<<<dim3(M_ / 64, C_ / 64), 256>>>(gfk, kp2_w, gf, gf, nullptr, M_, C_, PC_, 0);
    // pts = f + x0
    k_add<<<(M_ * C_ + 255) / 256, 256>>>(gf, gx0, gpts, M_ * C_);

    // ---- RWKV spatial mix ----
    k_ln<<<M_, 128>>>(gpts, ln1_g, ln1_b, gxn);
    k_mix<<<(M_ * C_ + 255) / 256, 256>>>(gxn, mix_k, mix_v, mix_r, gmk, gmv, gmr);
    k_gemm<<<dim3(M_ / 64, C_ / 64), 256>>>(gmk, att_wk, gkk, nullptr, nullptr, M_, C_, C_, 0);
    k_gemm<<<dim3(M_ / 64, C_ / 64), 256>>>(gmv, att_wv, gvv, nullptr, nullptr, M_, C_, C_, 0);
    k_gemm<<<dim3(M_ / 64, C_ / 64), 256>>>(gmr, att_wr, grr, nullptr, nullptr, M_, C_, C_, 1);
    k_transpose<<<tgrid, tb>>>(gkk, gkT);
    k_transpose<<<tgrid, tb>>>(gvv, gvT);
    k_wkv<<<32, 256>>>(gkT, gvT, grr, tdcy, tfst, gwkv);
    k_gemm<<<dim3(M_ / 64, C_ / 64), 256>>>(gwkv, att_wo, gpts, gpts, nullptr, M_, C_, C_, 0);

    // ---- channel mix ----
    k_ln<<<M_, 128>>>(gpts, ln2_g, ln2_b, gxn);
    k_mix<<<(M_ * C_ + 255) / 256, 256>>>(gxn, cmix_k, nullptr, cmix_r, gmk, nullptr, gmr);
    k_gemm<<<dim3(M_ / 64, F_ / 64), 256>>>(gmk, ffn_wk, gffn, nullptr, nullptr, M_, F_, C_, 2);
    k_gemm<<<dim3(M_ / 64, C_ / 64), 256>>>(gmr, ffn_wr, grr, nullptr, nullptr, M_, C_, C_, 1);
    k_gemm<<<dim3(M_ / 64, C_ / 64), 256>>>(gffn, ffn_wv, gpts, gpts, grr, M_, C_, F_, 0);

    // ---- outputs ----
    k_transpose<<<tgrid, tb>>>(gpts, out_y);          // y (pre-BN)
    k_bnpart<<<32, 128>>>(gpts);
    k_bnred<<<1, 128>>>(bn_g, bn_b);
    k_head<<<M_ / 8, 256>>>(gpts, conv_w, conv_b, out_label);
    (void)in_sizes; (void)n_in; (void)out_size;
}

// round 5
// speedup vs baseline: 2.2835x; 2.2835x over previous
#include <cuda_runtime.h>
#include <cuda_bf16.h>
#include <math.h>

static constexpr int B_ = 2, N_ = 4096, C_ = 128, K_ = 16, P_ = 43, CLS_ = 16, F_ = 512;
static constexpr int M_ = B_ * N_;
static constexpr int PC_ = P_ * C_;          // 5504
static constexpr float R2_ = 0.01f;          // RADIUS^2
static constexpr float INV_SIG_ = 10.0f;     // 1/RADIUS

// ---------------- static device scratch (no allocations) ----------------
__device__ float4 g_xyzw[M_];                // x,y,z,|p|^2
__device__ int    g_nbr[M_ * K_];
__device__ float  g_kpts[P_ * 3];
__device__ float  g_f[M_ * C_];
__device__ float  g_x0[M_ * C_];
__device__ __nv_bfloat16 g_fk_hi[(size_t)M_ * PC_];   // 90 MB
__device__ __nv_bfloat16 g_fk_lo[(size_t)M_ * PC_];   // 90 MB
__device__ __nv_bfloat16 g_wT_hi[(size_t)C_ * PC_];   // [d][q] = [n][k]
__device__ __nv_bfloat16 g_wT_lo[(size_t)C_ * PC_];
__device__ float g_pts[M_ * C_];
__device__ float g_xn[M_ * C_];
__device__ float g_mk[M_ * C_];
__device__ float g_mv[M_ * C_];
__device__ float g_mr[M_ * C_];
__device__ float g_kk[M_ * C_];
__device__ float g_vv[M_ * C_];
__device__ float g_rr[M_ * C_];
__device__ float g_kT[M_ * C_];
__device__ float g_vT[M_ * C_];
__device__ float g_wkv[M_ * C_];
__device__ float g_ffn[M_ * F_];
__device__ float g_p1[32 * C_];
__device__ float g_p2[32 * C_];
__device__ float g_bnA[C_];
__device__ float g_bnB[C_];

// ---------------- kernel points (fp64, matches numpy fibonacci sphere) ----------------
__global__ void k_init_kpts() {
    int t = threadIdx.x;
    if (t >= P_) return;
    double x = 0.0, y = 0.0, z = 0.0;
    if (t > 0) {
        int mc = (t <= 14) ? 14 : 28;
        double scale = (t <= 14) ? 0.05 : 0.1;
        int i0 = (t <= 14) ? (t - 1) : (t - 15);
        double i = i0 + 0.5;
        double phi = acos(1.0 - 2.0 * i / (double)mc);
        double theta = 3.141592653589793 * (1.0 + sqrt(5.0)) * i;
        x = cos(theta) * sin(phi) * scale;
        y = sin(theta) * sin(phi) * scale;
        z = cos(phi) * scale;
    }
    g_kpts[t * 3 + 0] = (float)x;
    g_kpts[t * 3 + 1] = (float)y;
    g_kpts[t * 3 + 2] = (float)z;
}

// ---------------- prep ----------------
__global__ void k_prep_xyz(const float* __restrict__ p) {
    int m = blockIdx.x * blockDim.x + threadIdx.x;
    if (m >= M_) return;
    int b = m / N_, n = m - b * N_;
    float x = p[((size_t)b * 3 + 0) * N_ + n];
    float y = p[((size_t)b * 3 + 1) * N_ + n];
    float z = p[((size_t)b * 3 + 2) * N_ + n];
    g_xyzw[m] = make_float4(x, y, z, fmaf(x, x, fmaf(y, y, z * z)));
}

__global__ void k_prep_feat(const float* __restrict__ x) {
    int i = blockIdx.x * blockDim.x + threadIdx.x;
    if (i >= M_ * C_) return;
    int m = i / C_, c = i - m * C_;
    int b = m / N_, n = m - b * N_;
    float v = x[((size_t)b * C_ + c) * N_ + n];
    g_f[i] = v;
    g_x0[i] = v;
}

// ---------------- radius-limited 16-NN: warp per query ----------------
__global__ void __launch_bounds__(256) k_knn() {
    int wid = threadIdx.x >> 5, lane = threadIdx.x & 31;
    int m = blockIdx.x * 8 + wid;            // 1024 blocks x 8 warps
    int b = m >> 12;
    int base = b * N_;
    float4 q = g_xyzw[m];
    float bd[K_]; int bi[K_];
#pragma unroll
    for (int k = 0; k < K_; k++) { bd[k] = 3.4e38f; bi[k] = 0x7FFFFFFF; }
    float worst = 3.4e38f;
    __shared__ float4 tile[1024];
    for (int t0 = 0; t0 < N_; t0 += 1024) {
        __syncthreads();
        for (int j = threadIdx.x; j < 1024; j += 256) tile[j] = g_xyzw[base + t0 + j];
        __syncthreads();
#pragma unroll 4
        for (int t = 0; t < 32; t++) {
            int j = t * 32 + lane;
            float4 c = tile[j];
            float dot = fmaf(q.x, c.x, fmaf(q.y, c.y, q.z * c.z));
            float d2 = q.w + c.w - 2.0f * dot;        // identical arithmetic everywhere
            if (d2 <= R2_ && d2 < worst) {
                int idx = t0 + j;
                int pos = K_ - 1;
                for (; pos > 0 && bd[pos - 1] > d2; pos--) {
                    bd[pos] = bd[pos - 1]; bi[pos] = bi[pos - 1];
                }
                bd[pos] = d2; bi[pos] = idx;
                worst = bd[K_ - 1];
            }
        }
    }
    // warp merge: 16 rounds of lexicographic (d2, idx) min
    int ptr = 0;
    float myd = 3.4e38f; int myi = 0;
    for (int r = 0; r < K_; r++) {
        float hd = (ptr < K_) ? bd[ptr] : 3.4e38f;
        int hidx = (ptr < K_) ? bi[ptr] : 0x7FFFFFFF;
        unsigned fb = __float_as_uint(hd);
        fb = (fb & 0x80000000u) ? ~fb : (fb | 0x80000000u);   // total order on floats
        unsigned long long key = (((unsigned long long)fb) << 32) | (unsigned)hidx;
#pragma unroll
        for (int off = 16; off >= 1; off >>= 1) {
            unsigned long long o = __shfl_xor_sync(0xffffffffu, key, off);
            if (o < key) key = o;
        }
        unsigned tu = (unsigned)(key >> 32);
        unsigned ob = (tu & 0x80000000u) ? (tu ^ 0x80000000u) : ~tu;
        float wd = __uint_as_float(ob);
        int wi_ = (int)(unsigned)(key & 0xffffffffu);
        if (ptr < K_ && hidx == wi_ && __float_as_uint(hd) == ob) ptr++;
        if (lane == r) { myd = wd; myi = wi_; }
    }
    int wi0 = __shfl_sync(0xffffffffu, myi, 0);
    if (lane < K_) {
        int sel = (myd <= R2_) ? myi : wi0;
        g_nbr[m * K_ + lane] = base + sel;
    }
}

// ---------------- build fk (bf16 hi/lo split) ----------------
__global__ void __launch_bounds__(128) k_build_fk(const float* __restrict__ fin) {
    int m = blockIdx.x;
    int tid = threadIdx.x;
    __shared__ float infl[K_][P_ + 5];
    __shared__ float nx[K_], ny[K_], nz[K_];
    __shared__ int nidx[K_];
    float4 cq = g_xyzw[m];
    if (tid < K_) {
        int nb = g_nbr[m * K_ + tid];
        nidx[tid] = nb;
        float4 nq = g_xyzw[nb];
        nx[tid] = nq.x; ny[tid] = nq.y; nz[tid] = nq.z;
    }
    __syncthreads();
    for (int e = tid; e < K_ * P_; e += 128) {
        int k = e / P_, pp = e - k * P_;
        float rx = nx[k] - cq.x, ry = ny[k] - cq.y, rz = nz[k] - cq.z;
        float dx = rx - g_kpts[pp * 3], dy = ry - g_kpts[pp * 3 + 1], dz = rz - g_kpts[pp * 3 + 2];
        float d = sqrtf(fmaf(dx, dx, fmaf(dy, dy, dz * dz)) + 1e-12f);
        infl[k][pp] = fmaxf(0.0f, 1.0f - d * INV_SIG_);
    }
    __syncthreads();
    float Fv[K_];
#pragma unroll
    for (int k = 0; k < K_; k++) Fv[k] = fin[(size_t)nidx[k] * C_ + tid];
    size_t dst = (size_t)m * PC_ + tid;
#pragma unroll 1
    for (int pp = 0; pp < P_; pp++) {
        float acc = 0.f;
#pragma unroll
        for (int k = 0; k < K_; k++) acc = fmaf(infl[k][pp], Fv[k], acc);
        __nv_bfloat16 h = __float2bfloat16(acc);
        float rem = acc - __bfloat162float(h);
        g_fk_hi[dst + (size_t)pp * C_] = h;
        g_fk_lo[dst + (size_t)pp * C_] = __float2bfloat16(rem);
    }
}

// ---------------- split + transpose kpconv weights: w[q, d] -> wT[d, q] hi/lo ----------------
__global__ void k_wsplit(const float* __restrict__ w) {
    int i = blockIdx.x * 256 + threadIdx.x;
    if (i >= C_ * PC_) return;
    int d = i / PC_, qq = i - d * PC_;
    float v = w[(size_t)qq * C_ + d];
    __nv_bfloat16 h = __float2bfloat16(v);
    g_wT_hi[i] = h;
    g_wT_lo[i] = __float2bfloat16(v - __bfloat162float(h));
}

// ---------------- HMMA bf16 split-precision KPConv GEMM ----------------
// Out[M,128] = fk[M,5504] @ wT^T + Res (+Res2)
// BM=64, BN=128, BK=32; 8 warps; warp tile 32x32 (2x4 m16n8k16)
static constexpr int GBK = 32;
static constexpr int NCH_ = PC_ / GBK;       // 172
static constexpr int ROWP = 40;              // padded row stride (bf16 elems)
// stage layout (bytes): Ahi[64*40*2]=5120, Alo=5120, Bhi[128*40*2]=10240, Blo=10240
static constexpr int ST_ALO = 5120;
static constexpr int ST_BHI = 10240;
static constexpr int ST_BLO = 20480;
static constexpr int ST_SZ  = 30720;
static constexpr int SM_MMA = 2 * ST_SZ;     // 61440

__device__ __forceinline__ void cp16(void* dst, const void* src) {
    unsigned d;
    asm("{ .reg .u64 t; cvta.to.shared.u64 t, %1; cvt.u32.u64 %0, t; }" : "=r"(d) : "l"(dst));
    asm volatile("cp.async.cg.shared.global [%0], [%1], 16;" :: "r"(d), "l"(src));
}
__device__ __forceinline__ void cp_commit() {
    asm volatile("cp.async.commit_group;" ::: "memory");
}
template <int N>
__device__ __forceinline__ void cp_wait() {
    asm volatile("cp.async.wait_group %0;" :: "n"(N) : "memory");
}
__device__ __forceinline__ void mma16816(float* c, const unsigned* a, const unsigned* b) {
    asm volatile(
        "mma.sync.aligned.m16n8k16.row.col.f32.bf16.bf16.f32 "
        "{%0,%1,%2,%3}, {%4,%5,%6,%7}, {%8,%9}, {%0,%1,%2,%3};"
        : "+f"(c[0]), "+f"(c[1]), "+f"(c[2]), "+f"(c[3])
        : "r"(a[0]), "r"(a[1]), "r"(a[2]), "r"(a[3]), "r"(b[0]), "r"(b[1]));
}

__global__ void __launch_bounds__(256) k_mma_kpconv(
    const float* __restrict__ Res, const float* __restrict__ Res2, float* __restrict__ Out)
{
    extern __shared__ char smem[];
    int tid = threadIdx.x;
    int bm = blockIdx.x * 64;
    int wid = tid >> 5, lane = tid & 31;
    int wm = wid & 1, wn = wid >> 1;         // warp: 32 rows x 32 cols
    int lr = lane >> 2;                      // 0..7
    int lk = (lane & 3) << 1;                // 0,2,4,6 (k elems)

    float acc[2][4][4];
#pragma unroll
    for (int i = 0; i < 2; i++)
#pragma unroll
        for (int j = 0; j < 4; j++)
#pragma unroll
            for (int q = 0; q < 4; q++) acc[i][j][q] = 0.f;

    // per-thread load indices
    int arow = tid >> 2, aseg = tid & 3;     // A: 64 rows x 4 16B-segs
    // issue loads for chunk ch into stage s
    auto load_chunk = [&](int ch, int s) {
        int k0 = ch * GBK;
        char* st = smem + s * ST_SZ;
        size_t asrc = (size_t)(bm + arow) * PC_ + k0 + aseg * 8;
        int adst = (arow * ROWP + aseg * 8) * 2;
        cp16(st + adst, g_fk_hi + asrc);
        cp16(st + ST_ALO + adst, g_fk_lo + asrc);
#pragma unroll
        for (int i = 0; i < 2; i++) {
            int idx = tid + i * 256;
            int brow = idx >> 2, bseg = idx & 3;
            size_t bsrc = (size_t)brow * PC_ + k0 + bseg * 8;
            int bdst = (brow * ROWP + bseg * 8) * 2;
            cp16(st + ST_BHI + bdst, g_wT_hi + bsrc);
            cp16(st + ST_BLO + bdst, g_wT_lo + bsrc);
        }
        cp_commit();
    };

    load_chunk(0, 0);
    for (int ch = 0; ch < NCH_; ch++) {
        int s = ch & 1;
        if (ch + 1 < NCH_) { load_chunk(ch + 1, s ^ 1); cp_wait<1>(); }
        else cp_wait<0>();
        __syncthreads();
        const char* st = smem + s * ST_SZ;
#pragma unroll
        for (int ks = 0; ks < 2; ks++) {
            int kb = ks * 16;
            unsigned ahi[2][4], alo[2][4], bhi[4][2], blo[4][2];
#pragma unroll
            for (int mt = 0; mt < 2; mt++) {
                int r0 = wm * 32 + mt * 16 + lr;
                int o00 = (r0 * ROWP + kb + lk) * 2;
                int o10 = ((r0 + 8) * ROWP + kb + lk) * 2;
                ahi[mt][0] = *(const unsigned*)(st + o00);
                ahi[mt][1] = *(const unsigned*)(st + o10);
                ahi[mt][2] = *(const unsigned*)(st + o00 + 16);
                ahi[mt][3] = *(const unsigned*)(st + o10 + 16);
                alo[mt][0] = *(const unsigned*)(st + ST_ALO + o00);
                alo[mt][1] = *(const unsigned*)(st + ST_ALO + o10);
                alo[mt][2] = *(const unsigned*)(st + ST_ALO + o00 + 16);
                alo[mt][3] = *(const unsigned*)(st + ST_ALO + o10 + 16);
            }
#pragma unroll
            for (int nt = 0; nt < 4; nt++) {
                int n0 = wn * 32 + nt * 8 + lr;
                int ob = (n0 * ROWP + kb + lk) * 2;
                bhi[nt][0] = *(const unsigned*)(st + ST_BHI + ob);
                bhi[nt][1] = *(const unsigned*)(st + ST_BHI + ob + 16);
                blo[nt][0] = *(const unsigned*)(st + ST_BLO + ob);
                blo[nt][1] = *(const unsigned*)(st + ST_BLO + ob + 16);
            }
#pragma unroll
            for (int mt = 0; mt < 2; mt++)
#pragma unroll
                for (int nt = 0; nt < 4; nt++) {
                    mma16816(acc[mt][nt], ahi[mt], bhi[nt]);
                    mma16816(acc[mt][nt], ahi[mt], blo[nt]);
                    mma16816(acc[mt][nt], alo[mt], bhi[nt]);
                }
        }
        __syncthreads();
    }

    // epilogue
#pragma unroll
    for (int mt = 0; mt < 2; mt++) {
#pragma unroll
        for (int nt = 0; nt < 4; nt++) {
            int col = wn * 32 + nt * 8 + ((lane & 3) << 1);
#pragma unroll
            for (int h = 0; h < 2; h++) {
                int row = bm + wm * 32 + mt * 16 + lr + h * 8;
                size_t o = (size_t)row * C_ + col;
                float v0 = acc[mt][nt][h * 2 + 0] + Res[o];
                float v1 = acc[mt][nt][h * 2 + 1] + Res[o + 1];
                if (Res2) { v0 += Res2[o]; v1 += Res2[o + 1]; }
                *(float2*)(Out + o) = make_float2(v0, v1);
            }
        }
    }
}

// ---------------- generic fp32 GEMM (small ones): out = ep(A@B) * Mul + Res ----------------
__global__ void __launch_bounds__(256) k_gemm(
    const float* __restrict__ A, const float* __restrict__ Bm, float* __restrict__ Cm,
    const float* __restrict__ Res, const float* __restrict__ Mul,
    int Md, int Nd, int Kd, int ep)
{
    __shared__ float As[16][68];
    __shared__ float Bs[16][68];
    int bm = blockIdx.x * 64;
    int bn = blockIdx.y * 64;
    int tid = threadIdx.x;
    int ar = tid >> 2, ak = (tid & 3) << 2;
    int bk = tid >> 4, bc = (tid & 15) << 2;
    int tx = (tid & 15) << 2, ty = (tid >> 4) << 2;
    float acc[4][4];
#pragma unroll
    for (int i = 0; i < 4; i++)
#pragma unroll
        for (int j = 0; j < 4; j++) acc[i][j] = 0.f;
    const float* Ap = A + (size_t)(bm + ar) * Kd + ak;
    const float* Bp = Bm + (size_t)bk * Nd + bn + bc;
    for (int k0 = 0; k0 < Kd; k0 += 16) {
        float4 a4 = *(const float4*)(Ap + k0);
        float4 b4 = *(const float4*)(Bp + (size_t)k0 * Nd);
        __syncthreads();
        As[ak + 0][ar] = a4.x; As[ak + 1][ar] = a4.y;
        As[ak + 2][ar] = a4.z; As[ak + 3][ar] = a4.w;
        *(float4*)&Bs[bk][bc] = b4;
        __syncthreads();
#pragma unroll
        for (int kk = 0; kk < 16; kk++) {
            float4 av = *(const float4*)&As[kk][ty];
            float4 bv = *(const float4*)&Bs[kk][tx];
            float a0 = av.x, a1 = av.y, a2 = av.z, a3 = av.w;
            float b0 = bv.x, b1 = bv.y, b2 = bv.z, b3 = bv.w;
            acc[0][0] = fmaf(a0, b0, acc[0][0]); acc[0][1] = fmaf(a0, b1, acc[0][1]);
            acc[0][2] = fmaf(a0, b2, acc[0][2]); acc[0][3] = fmaf(a0, b3, acc[0][3]);
            acc[1][0] = fmaf(a1, b0, acc[1][0]); acc[1][1] = fmaf(a1, b1, acc[1][1]);
            acc[1][2] = fmaf(a1, b2, acc[1][2]); acc[1][3] = fmaf(a1, b3, acc[1][3]);
            acc[2][0] = fmaf(a2, b0, acc[2][0]); acc[2][1] = fmaf(a2, b1, acc[2][1]);
            acc[2][2] = fmaf(a2, b2, acc[2][2]); acc[2][3] = fmaf(a2, b3, acc[2][3]);
            acc[3][0] = fmaf(a3, b0, acc[3][0]); acc[3][1] = fmaf(a3, b1, acc[3][1]);
            acc[3][2] = fmaf(a3, b2, acc[3][2]); acc[3][3] = fmaf(a3, b3, acc[3][3]);
        }
    }
#pragma unroll
    for (int i = 0; i < 4; i++) {
        size_t row = (size_t)(bm + ty + i);
#pragma unroll
        for (int j = 0; j < 4; j++) {
            size_t idx = row * Nd + bn + tx + j;
            float v = acc[i][j];
            if (ep == 1) v = 1.0f / (1.0f + __expf(-v));
            else if (ep == 2) { v = fmaxf(v, 0.f); v = v * v; }
            if (Mul) v *= Mul[idx];
            if (Res) v += Res[idx];
            Cm[idx] = v;
        }
    }
}

// ---------------- LayerNorm over last dim (C=128) ----------------
__global__ void __launch_bounds__(128) k_ln(const float* __restrict__ X,
                                            const float* __restrict__ g,
                                            const float* __restrict__ bb,
                                            float* __restrict__ Y) {
    int m = blockIdx.x, c = threadIdx.x;
    float v = X[(size_t)m * C_ + c];
    float s = v, q = v * v;
#pragma unroll
    for (int off = 16; off >= 1; off >>= 1) {
        s += __shfl_xor_sync(0xffffffffu, s, off);
        q += __shfl_xor_sync(0xffffffffu, q, off);
    }
    __shared__ float s1[4], s2[4];
    int w = c >> 5;
    if ((c & 31) == 0) { s1[w] = s; s2[w] = q; }
    __syncthreads();
    s = s1[0] + s1[1] + s1[2] + s1[3];
    q = s2[0] + s2[1] + s2[2] + s2[3];
    float mu = s * (1.0f / C_);
    float var = q * (1.0f / C_) - mu * mu;
    Y[(size_t)m * C_ + c] = (v - mu) * rsqrtf(var + 1e-5f) * g[c] + bb[c];
}

// ---------------- token-shift mix ----------------
__global__ void k_mix(const float* __restrict__ xn,
                      const float* __restrict__ mk, const float* __restrict__ mv,
                      const float* __restrict__ mr,
                      float* __restrict__ ok, float* __restrict__ ov, float* __restrict__ orr) {
    int i = blockIdx.x * blockDim.x + threadIdx.x;
    if (i >= M_ * C_) return;
    int m = i >> 7, c = i & 127;
    int n = m & (N_ - 1);
    float xc = xn[i];
    float xp = (n == 0) ? 0.f : xn[i - C_];
    float a = mk[c]; ok[i] = xc * a + xp * (1.f - a);
    if (ov) { a = mv[c]; ov[i] = xc * a + xp * (1.f - a); }
    a = mr[c]; orr[i] = xc * a + xp * (1.f - a);
}

// ---------------- transpose [b,n,c] -> [b,c,n] ----------------
__global__ void k_transpose(const float* __restrict__ in, float* __restrict__ out) {
    __shared__ float t[32][33];
    int b = blockIdx.z;
    int n0 = blockIdx.x * 32, c0 = blockIdx.y * 32;
    int x = threadIdx.x, y = threadIdx.y;   // 32 x 8
    for (int i = y; i < 32; i += 8)
        t[i][x] = in[((size_t)(b * N_ + n0 + i)) * C_ + c0 + x];
    __syncthreads();
    for (int i = y; i < 32; i += 8)
        out[((size_t)(b * C_ + c0 + i)) * N_ + n0 + x] = t[x][i];
}

// ---------------- WKV: warp per (b,c), affine chunked scan ----------------
__global__ void __launch_bounds__(256) k_wkv(
    const float* __restrict__ kT, const float* __restrict__ vT,
    const float* __restrict__ sigr,
    const float* __restrict__ td, const float* __restrict__ tf,
    float* __restrict__ out)
{
    int warp = (blockIdx.x * 256 + threadIdx.x) >> 5;
    int lane = threadIdx.x & 31;
    int b = warp >> 7, c = warp & 127;
    float w = -expf(td[c]);
    float ew = expf(w);
    float etf = expf(tf[c]);
    int n0 = lane * 128;
    const float* kp = kT + ((size_t)(b * C_ + c)) * N_ + n0;
    const float* vp = vT + ((size_t)(b * C_ + c)) * N_ + n0;
    float A = 0.f, Bv = 0.f;
#pragma unroll 4
    for (int j = 0; j < 128; j++) {
        float ek = __expf(kp[j]);
        A = fmaf(A, ew, ek * vp[j]);
        Bv = fmaf(Bv, ew, ek);
    }
    float al = __expf(128.0f * w);
    float sA = A, sB = Bv, sal = al;
#pragma unroll
    for (int off = 1; off < 32; off <<= 1) {
        float pA = __shfl_up_sync(0xffffffffu, sA, off);
        float pB = __shfl_up_sync(0xffffffffu, sB, off);
        float pal = __shfl_up_sync(0xffffffffu, sal, off);
        if (lane >= off) {
            sA = fmaf(sal, pA, sA);
            sB = fmaf(sal, pB, sB);
            sal = sal * pal;
        }
    }
    float A0 = __shfl_up_sync(0xffffffffu, sA, 1);
    float B0 = __shfl_up_sync(0xffffffffu, sB, 1);
    if (lane == 0) { A0 = 0.f; B0 = 0.f; }
    A = A0; Bv = B0;
    const float* rp = sigr + ((size_t)(b * N_ + n0)) * C_ + c;
    float* op = out + ((size_t)(b * N_ + n0)) * C_ + c;
#pragma unroll 2
    for (int j = 0; j < 128; j++) {
        float kt = kp[j], vt = vp[j];
        float ek = __expf(kt);
        float ekf = etf * ek;
        float o = (A + ekf * vt) / (Bv + ekf);
        op[(size_t)j * C_] = o * rp[(size_t)j * C_];
        A = fmaf(A, ew, ek * vt);
        Bv = fmaf(Bv, ew, ek);
    }
}

// ---------------- BN stats: deterministic two-stage ----------------
__global__ void __launch_bounds__(128) k_bnpart(const float* __restrict__ pts) {
    int blk = blockIdx.x;
    int c = threadIdx.x;
    float s = 0.f, q = 0.f;
    int base = blk * 256;
    for (int r = 0; r < 256; r++) {
        float v = pts[(size_t)(base + r) * C_ + c];
        s += v; q = fmaf(v, v, q);
    }
    g_p1[blk * C_ + c] = s;
    g_p2[blk * C_ + c] = q;
}

__global__ void __launch_bounds__(128) k_bnred(const float* __restrict__ bg,
                                               const float* __restrict__ bb) {
    int c = threadIdx.x;
    float s = 0.f, q = 0.f;
    for (int i = 0; i < 32; i++) { s += g_p1[i * C_ + c]; q += g_p2[i * C_ + c]; }
    float mu = s * (1.0f / M_);
    float var = q * (1.0f / M_) - mu * mu;
    float a = bg[c] * rsqrtf(var + 1e-5f);
    g_bnA[c] = a;
    g_bnB[c] = bb[c] - mu * a;
}

// ---------------- head ----------------
__global__ void __launch_bounds__(256) k_head(const float* __restrict__ pts,
                                              const float* __restrict__ cw,
                                              const float* __restrict__ cb,
                                              float* __restrict__ label) {
    __shared__ float sw[CLS_ * C_];
    int tid = threadIdx.x;
    for (int i = tid; i < CLS_ * C_; i += 256) sw[i] = cw[i];
    __syncthreads();
    int m = blockIdx.x * 8 + (tid >> 5);
    int lane = tid & 31;
    float yn[4];
#pragma unroll
    for (int j = 0; j < 4; j++) {
        int c = lane + 32 * j;
        float v = fmaf(g_bnA[c], pts[(size_t)m * C_ + c], g_bnB[c]);
        yn[j] = fmaxf(v, 0.f);
    }
    int b = m >> 12, n = m & (N_ - 1);
#pragma unroll 1
    for (int d = 0; d < CLS_; d++) {
        float p = 0.f;
#pragma unroll
        for (int j = 0; j < 4; j++) p = fmaf(yn[j], sw[d * C_ + lane + 32 * j], p);
#pragma unroll
        for (int off = 16; off >= 1; off >>= 1) p += __shfl_xor_sync(0xffffffffu, p, off);
        if (lane == 0)
            label[((size_t)(b * CLS_ + d)) * N_ + n] = p + cb[d];
    }
}

// ---------------- host ----------------
extern "C" void kernel_launch(void* const* d_in, const int* in_sizes, int n_in,
                              void* d_out, int out_size) {
    const float* p        = (const float*)d_in[0];
    const float* x        = (const float*)d_in[1];
    const float* kp1_w    = (const float*)d_in[2];
    const float* kp2_w    = (const float*)d_in[3];
    const float* ln1_g    = (const float*)d_in[4];
    const float* ln1_b    = (const float*)d_in[5];
    const float* tdcy     = (const float*)d_in[6];
    const float* tfst     = (const float*)d_in[7];
    const float* mix_k    = (const float*)d_in[8];
    const float* mix_v    = (const float*)d_in[9];
    const float* mix_r    = (const float*)d_in[10];
    const float* att_wk   = (const float*)d_in[11];
    const float* att_wv   = (const float*)d_in[12];
    const float* att_wr   = (const float*)d_in[13];
    const float* att_wo   = (const float*)d_in[14];
    const float* ln2_g    = (const float*)d_in[15];
    const float* ln2_b    = (const float*)d_in[16];
    const float* cmix_k   = (const float*)d_in[17];
    const float* cmix_r   = (const float*)d_in[18];
    const float* ffn_wk   = (const float*)d_in[19];
    const float* ffn_wv   = (const float*)d_in[20];
    const float* ffn_wr   = (const float*)d_in[21];
    const float* bn_g     = (const float*)d_in[22];
    const float* bn_b     = (const float*)d_in[23];
    const float* conv_w   = (const float*)d_in[24];
    const float* conv_b   = (const float*)d_in[25];

    float* out_y = (float*)d_out;
    float* out_label = out_y + (size_t)B_ * C_ * N_;

    float *gf, *gx0, *gpts, *gxn, *gmk, *gmv, *gmr;
    float *gkk, *gvv, *grr, *gkT, *gvT, *gwkv, *gffn;
    cudaGetSymbolAddress((void**)&gf, g_f);
    cudaGetSymbolAddress((void**)&gx0, g_x0);
    cudaGetSymbolAddress((void**)&gpts, g_pts);
    cudaGetSymbolAddress((void**)&gxn, g_xn);
    cudaGetSymbolAddress((void**)&gmk, g_mk);
    cudaGetSymbolAddress((void**)&gmv, g_mv);
    cudaGetSymbolAddress((void**)&gmr, g_mr);
    cudaGetSymbolAddress((void**)&gkk, g_kk);
    cudaGetSymbolAddress((void**)&gvv, g_vv);
    cudaGetSymbolAddress((void**)&grr, g_rr);
    cudaGetSymbolAddress((void**)&gkT, g_kT);
    cudaGetSymbolAddress((void**)&gvT, g_vT);
    cudaGetSymbolAddress((void**)&gwkv, g_wkv);
    cudaGetSymbolAddress((void**)&gffn, g_ffn);

    cudaFuncSetAttribute(k_mma_kpconv, cudaFuncAttributeMaxDynamicSharedMemorySize, SM_MMA);

    dim3 tb(32, 8);
    dim3 tgrid(N_ / 32, C_ / 32, B_);

    k_init_kpts<<<1, 64>>>();
    k_prep_xyz<<<(M_ + 255) / 256, 256>>>(p);
    k_prep_feat<<<(M_ * C_ + 255) / 256, 256>>>(x);
    k_knn<<<M_ / 8, 256>>>();

    // KPConv 1 (HMMA tensor cores): f1 = fk(f0) @ w1 + f0
    k_wsplit<<<(C_ * PC_ + 255) / 256, 256>>>(kp1_w);
    k_build_fk<<<M_, 128>>>(gf);
    k_mma_kpconv<<<M_ / 64, 256, SM_MMA>>>(gf, nullptr, gf);
    // KPConv 2: pts = fk(f1) @ w2 + f1 + x0
    k_wsplit<<<(C_ * PC_ + 255) / 256, 256>>>(kp2_w);
    k_build_fk<<<M_, 128>>>(gf);
    k_mma_kpconv<<<M_ / 64, 256, SM_MMA>>>(gf, gx0, gpts);

    // ---- RWKV spatial mix ----
    k_ln<<<M_, 128>>>(gpts, ln1_g, ln1_b, gxn);
    k_mix<<<(M_ * C_ + 255) / 256, 256>>>(gxn, mix_k, mix_v, mix_r, gmk, gmv, gmr);
    k_gemm<<<dim3(M_ / 64, C_ / 64), 256>>>(gmk, att_wk, gkk, nullptr, nullptr, M_, C_, C_, 0);
    k_gemm<<<dim3(M_ / 64, C_ / 64), 256>>>(gmv, att_wv, gvv, nullptr, nullptr, M_, C_, C_, 0);
    k_gemm<<<dim3(M_ / 64, C_ / 64), 256>>>(gmr, att_wr, grr, nullptr, nullptr, M_, C_, C_, 1);
    k_transpose<<<tgrid, tb>>>(gkk, gkT);
    k_transpose<<<tgrid, tb>>>(gvv, gvT);
    k_wkv<<<32, 256>>>(gkT, gvT, grr, tdcy, tfst, gwkv);
    k_gemm<<<dim3(M_ / 64, C_ / 64), 256>>>(gwkv, att_wo, gpts, gpts, nullptr, M_, C_, C_, 0);

    // ---- channel mix ----
    k_ln<<<M_, 128>>>(gpts, ln2_g, ln2_b, gxn);
    k_mix<<<(M_ * C_ + 255) / 256, 256>>>(gxn, cmix_k, nullptr, cmix_r, gmk, nullptr, gmr);
    k_gemm<<<dim3(M_ / 64, F_ / 64), 256>>>(gmk, ffn_wk, gffn, nullptr, nullptr, M_, F_, C_, 2);
    k_gemm<<<dim3(M_ / 64, C_ / 64), 256>>>(gmr, ffn_wr, grr, nullptr, nullptr, M_, C_, C_, 1);
    k_gemm<<<dim3(M_ / 64, C_ / 64), 256>>>(gffn, ffn_wv, gpts, gpts, grr, M_, C_, F_, 0);

    // ---- outputs ----
    k_transpose<<<tgrid, tb>>>(gpts, out_y);
    k_bnpart<<<32, 128>>>(gpts);
    k_bnred<<<1, 128>>>(bn_g, bn_b);
    k_head<<<M_ / 8, 256>>>(gpts, conv_w, conv_b, out_label);
    (void)in_sizes; (void)n_in; (void)out_size;
}

// round 6
// speedup vs baseline: 2.5838x; 1.1315x over previous
#include <cuda_runtime.h>
#include <cuda_bf16.h>
#include <math.h>

static constexpr int B_ = 2, N_ = 4096, C_ = 128, K_ = 16, P_ = 43, CLS_ = 16, F_ = 512;
static constexpr int M_ = B_ * N_;
static constexpr int PC_ = P_ * C_;          // 5504
static constexpr float R2_ = 0.01f;          // RADIUS^2
static constexpr float INV_SIG_ = 10.0f;     // 1/RADIUS

// ---------------- static device scratch (no allocations) ----------------
__device__ float4 g_xyzw[M_];                // x,y,z,|p|^2
__device__ int    g_nbr[M_ * K_];
__device__ float  g_kpts[P_ * 3];
__device__ float  g_f[M_ * C_];
__device__ float  g_x0[M_ * C_];
__device__ __nv_bfloat16 g_fk_hi[(size_t)M_ * PC_];   // 90 MB
__device__ __nv_bfloat16 g_fk_lo[(size_t)M_ * PC_];   // 90 MB
__device__ __nv_bfloat16 g_wT_hi[(size_t)C_ * PC_];   // [d][q]
__device__ __nv_bfloat16 g_wT_lo[(size_t)C_ * PC_];
__device__ float g_pts[M_ * C_];
__device__ float g_xn[M_ * C_];
__device__ float g_kk[M_ * C_];     // unused spare
__device__ float g_rr[M_ * C_];
__device__ float g_kT[M_ * C_];
__device__ float g_vT[M_ * C_];
__device__ float g_wkv[M_ * C_];
__device__ float g_ffn[M_ * F_];
__device__ float g_p1[256 * C_];
__device__ float g_p2[256 * C_];
__device__ float g_bnA[C_];
__device__ float g_bnB[C_];

// ---------------- kernel points (fp64, matches numpy fibonacci sphere) ----------------
__global__ void k_init_kpts() {
    int t = threadIdx.x;
    if (t >= P_) return;
    double x = 0.0, y = 0.0, z = 0.0;
    if (t > 0) {
        int mc = (t <= 14) ? 14 : 28;
        double scale = (t <= 14) ? 0.05 : 0.1;
        int i0 = (t <= 14) ? (t - 1) : (t - 15);
        double i = i0 + 0.5;
        double phi = acos(1.0 - 2.0 * i / (double)mc);
        double theta = 3.141592653589793 * (1.0 + sqrt(5.0)) * i;
        x = cos(theta) * sin(phi) * scale;
        y = sin(theta) * sin(phi) * scale;
        z = cos(phi) * scale;
    }
    g_kpts[t * 3 + 0] = (float)x;
    g_kpts[t * 3 + 1] = (float)y;
    g_kpts[t * 3 + 2] = (float)z;
}

// ---------------- prep ----------------
__global__ void k_prep_xyz(const float* __restrict__ p) {
    int m = blockIdx.x * blockDim.x + threadIdx.x;
    if (m >= M_) return;
    int b = m / N_, n = m - b * N_;
    float x = p[((size_t)b * 3 + 0) * N_ + n];
    float y = p[((size_t)b * 3 + 1) * N_ + n];
    float z = p[((size_t)b * 3 + 2) * N_ + n];
    g_xyzw[m] = make_float4(x, y, z, fmaf(x, x, fmaf(y, y, z * z)));
}

// coalesced transpose x[b,c,n] -> f/x0 [b*n, c]
__global__ void k_prep_feat(const float* __restrict__ x) {
    __shared__ float t[32][33];
    int b = blockIdx.z;
    int c0 = blockIdx.x * 32, n0 = blockIdx.y * 32;
    int tx = threadIdx.x, ty = threadIdx.y;   // 32 x 8
    for (int i = ty; i < 32; i += 8)
        t[i][tx] = x[((size_t)(b * C_ + c0 + i)) * N_ + n0 + tx];
    __syncthreads();
    for (int i = ty; i < 32; i += 8) {
        float v = t[tx][i];
        size_t o = ((size_t)(b * N_ + n0 + i)) * C_ + c0 + tx;
        g_f[o] = v;
        g_x0[o] = v;
    }
}

// ---------------- radius-limited 16-NN: warp per query, register-only top-K ----------------
__global__ void __launch_bounds__(256) k_knn() {
    int wid = threadIdx.x >> 5, lane = threadIdx.x & 31;
    int m = blockIdx.x * 8 + wid;            // 1024 blocks x 8 warps
    int base = (m >> 12) * N_;
    float4 q = g_xyzw[m];
    float bd[K_]; int bi[K_];
#pragma unroll
    for (int k = 0; k < K_; k++) { bd[k] = 3.4e38f; bi[k] = 0x7FFFFFFF; }
    __shared__ float4 tile[1024];
    for (int t0 = 0; t0 < N_; t0 += 1024) {
        __syncthreads();
        for (int j = threadIdx.x; j < 1024; j += 256) tile[j] = g_xyzw[base + t0 + j];
        __syncthreads();
#pragma unroll 2
        for (int t = 0; t < 32; t++) {
            int j = t * 32 + lane;
            float4 c = tile[j];
            float dot = fmaf(q.x, c.x, fmaf(q.y, c.y, q.z * c.z));
            float d2 = q.w + c.w - 2.0f * dot;        // identical arithmetic everywhere
            if (d2 <= R2_ && d2 < bd[K_ - 1]) {
                int idx = t0 + j;
                // static-index predicated insertion (stable: strict '>' both ways)
#pragma unroll
                for (int k = K_ - 1; k >= 0; k--) {
                    float pd = (k > 0) ? bd[k - 1] : -1.0f;   // -1 < any d2 (>= -eps)
                    if (pd > d2) {
                        if (k > 0) { bd[k] = bd[k - 1]; bi[k] = bi[k - 1]; }
                    } else if (bd[k] > d2) {
                        bd[k] = d2; bi[k] = idx;
                    }
                }
            }
        }
    }
    // warp merge: 16 rounds; each lane always exposes bd[0] (static index)
    float outd = 3.4e38f; int outi = 0x7FFFFFFF;
    for (int r = 0; r < K_; r++) {
        unsigned fb = __float_as_uint(bd[0]);
        fb = (fb & 0x80000000u) ? ~fb : (fb | 0x80000000u);   // total order on floats
        unsigned long long key = (((unsigned long long)fb) << 32) | (unsigned)bi[0];
        unsigned long long kmin = key;
#pragma unroll
        for (int off = 16; off >= 1; off >>= 1) {
            unsigned long long o = __shfl_xor_sync(0xffffffffu, kmin, off);
            if (o < kmin) kmin = o;
        }
        if (key == kmin) {       // consume head: static shift-down
#pragma unroll
            for (int k = 0; k < K_ - 1; k++) { bd[k] = bd[k + 1]; bi[k] = bi[k + 1]; }
            bd[K_ - 1] = 3.4e38f; bi[K_ - 1] = 0x7FFFFFFF;
        }
        if (lane == r) {
            unsigned tu = (unsigned)(kmin >> 32);
            unsigned ob = (tu & 0x80000000u) ? (tu ^ 0x80000000u) : ~tu;
            outd = __uint_as_float(ob);
            outi = (int)(unsigned)(kmin & 0xffffffffu);
        }
    }
    int wi0 = __shfl_sync(0xffffffffu, outi, 0);
    if (lane < K_) {
        int sel = (outd <= R2_) ? outi : wi0;
        g_nbr[m * K_ + lane] = base + sel;
    }
}

// ---------------- build fk (bf16 hi/lo split) ----------------
__global__ void __launch_bounds__(128) k_build_fk(const float* __restrict__ fin) {
    int m = blockIdx.x;
    int tid = threadIdx.x;
    __shared__ float infl[K_][P_ + 5];
    __shared__ float nx[K_], ny[K_], nz[K_];
    __shared__ int nidx[K_];
    float4 cq = g_xyzw[m];
    if (tid < K_) {
        int nb = g_nbr[m * K_ + tid];
        nidx[tid] = nb;
        float4 nq = g_xyzw[nb];
        nx[tid] = nq.x; ny[tid] = nq.y; nz[tid] = nq.z;
    }
    __syncthreads();
    for (int e = tid; e < K_ * P_; e += 128) {
        int k = e / P_, pp = e - k * P_;
        float rx = nx[k] - cq.x, ry = ny[k] - cq.y, rz = nz[k] - cq.z;
        float dx = rx - g_kpts[pp * 3], dy = ry - g_kpts[pp * 3 + 1], dz = rz - g_kpts[pp * 3 + 2];
        float d = sqrtf(fmaf(dx, dx, fmaf(dy, dy, dz * dz)) + 1e-12f);
        infl[k][pp] = fmaxf(0.0f, 1.0f - d * INV_SIG_);
    }
    __syncthreads();
    float Fv[K_];
#pragma unroll
    for (int k = 0; k < K_; k++) Fv[k] = fin[(size_t)nidx[k] * C_ + tid];
    size_t dst = (size_t)m * PC_ + tid;
#pragma unroll 1
    for (int pp = 0; pp < P_; pp++) {
        float acc = 0.f;
#pragma unroll
        for (int k = 0; k < K_; k++) acc = fmaf(infl[k][pp], Fv[k], acc);
        __nv_bfloat16 h = __float2bfloat16(acc);
        float rem = acc - __bfloat162float(h);
        g_fk_hi[dst + (size_t)pp * C_] = h;
        g_fk_lo[dst + (size_t)pp * C_] = __float2bfloat16(rem);
    }
}

// ---------------- split + transpose kpconv weights ----------------
__global__ void k_wsplit(const float* __restrict__ w) {
    int i = blockIdx.x * 256 + threadIdx.x;
    if (i >= C_ * PC_) return;
    int d = i / PC_, qq = i - d * PC_;
    float v = w[(size_t)qq * C_ + d];
    __nv_bfloat16 h = __float2bfloat16(v);
    g_wT_hi[i] = h;
    g_wT_lo[i] = __float2bfloat16(v - __bfloat162float(h));
}

// ---------------- HMMA bf16 split-precision KPConv GEMM ----------------
static constexpr int GBK = 32;
static constexpr int NCH_ = PC_ / GBK;       // 172
static constexpr int ROWP = 40;              // padded row stride (bf16 elems)
static constexpr int ST_ALO = 5120;
static constexpr int ST_BHI = 10240;
static constexpr int ST_BLO = 20480;
static constexpr int ST_SZ  = 30720;
static constexpr int SM_MMA = 2 * ST_SZ;     // 61440

__device__ __forceinline__ void cp16(void* dst, const void* src) {
    unsigned d;
    asm("{ .reg .u64 t; cvta.to.shared.u64 t, %1; cvt.u32.u64 %0, t; }" : "=r"(d) : "l"(dst));
    asm volatile("cp.async.cg.shared.global [%0], [%1], 16;" :: "r"(d), "l"(src));
}
__device__ __forceinline__ void cp_commit() {
    asm volatile("cp.async.commit_group;" ::: "memory");
}
template <int N>
__device__ __forceinline__ void cp_wait() {
    asm volatile("cp.async.wait_group %0;" :: "n"(N) : "memory");
}
__device__ __forceinline__ void mma16816(float* c, const unsigned* a, const unsigned* b) {
    asm volatile(
        "mma.sync.aligned.m16n8k16.row.col.f32.bf16.bf16.f32 "
        "{%0,%1,%2,%3}, {%4,%5,%6,%7}, {%8,%9}, {%0,%1,%2,%3};"
        : "+f"(c[0]), "+f"(c[1]), "+f"(c[2]), "+f"(c[3])
        : "r"(a[0]), "r"(a[1]), "r"(a[2]), "r"(a[3]), "r"(b[0]), "r"(b[1]));
}

__global__ void __launch_bounds__(256) k_mma_kpconv(
    const float* __restrict__ Res, const float* __restrict__ Res2, float* __restrict__ Out)
{
    extern __shared__ char smem[];
    int tid = threadIdx.x;
    int bm = blockIdx.x * 64;
    int wid = tid >> 5, lane = tid & 31;
    int wm = wid & 1, wn = wid >> 1;
    int lr = lane >> 2;
    int lk = (lane & 3) << 1;

    float acc[2][4][4];
#pragma unroll
    for (int i = 0; i < 2; i++)
#pragma unroll
        for (int j = 0; j < 4; j++)
#pragma unroll
            for (int q = 0; q < 4; q++) acc[i][j][q] = 0.f;

    int arow = tid >> 2, aseg = tid & 3;
    auto load_chunk = [&](int ch, int s) {
        int k0 = ch * GBK;
        char* st = smem + s * ST_SZ;
        size_t asrc = (size_t)(bm + arow) * PC_ + k0 + aseg * 8;
        int adst = (arow * ROWP + aseg * 8) * 2;
        cp16(st + adst, g_fk_hi + asrc);
        cp16(st + ST_ALO + adst, g_fk_lo + asrc);
#pragma unroll
        for (int i = 0; i < 2; i++) {
            int idx = tid + i * 256;
            int brow = idx >> 2, bseg = idx & 3;
            size_t bsrc = (size_t)brow * PC_ + k0 + bseg * 8;
            int bdst = (brow * ROWP + bseg * 8) * 2;
            cp16(st + ST_BHI + bdst, g_wT_hi + bsrc);
            cp16(st + ST_BLO + bdst, g_wT_lo + bsrc);
        }
        cp_commit();
    };

    load_chunk(0, 0);
    for (int ch = 0; ch < NCH_; ch++) {
        int s = ch & 1;
        if (ch + 1 < NCH_) { load_chunk(ch + 1, s ^ 1); cp_wait<1>(); }
        else cp_wait<0>();
        __syncthreads();
        const char* st = smem + s * ST_SZ;
#pragma unroll
        for (int ks = 0; ks < 2; ks++) {
            int kb = ks * 16;
            unsigned ahi[2][4], alo[2][4], bhi[4][2], blo[4][2];
#pragma unroll
            for (int mt = 0; mt < 2; mt++) {
                int r0 = wm * 32 + mt * 16 + lr;
                int o00 = (r0 * ROWP + kb + lk) * 2;
                int o10 = ((r0 + 8) * ROWP + kb + lk) * 2;
                ahi[mt][0] = *(const unsigned*)(st + o00);
                ahi[mt][1] = *(const unsigned*)(st + o10);
                ahi[mt][2] = *(const unsigned*)(st + o00 + 16);
                ahi[mt][3] = *(const unsigned*)(st + o10 + 16);
                alo[mt][0] = *(const unsigned*)(st + ST_ALO + o00);
                alo[mt][1] = *(const unsigned*)(st + ST_ALO + o10);
                alo[mt][2] = *(const unsigned*)(st + ST_ALO + o00 + 16);
                alo[mt][3] = *(const unsigned*)(st + ST_ALO + o10 + 16);
            }
#pragma unroll
            for (int nt = 0; nt < 4; nt++) {
                int n0 = wn * 32 + nt * 8 + lr;
                int ob = (n0 * ROWP + kb + lk) * 2;
                bhi[nt][0] = *(const unsigned*)(st + ST_BHI + ob);
                bhi[nt][1] = *(const unsigned*)(st + ST_BHI + ob + 16);
                blo[nt][0] = *(const unsigned*)(st + ST_BLO + ob);
                blo[nt][1] = *(const unsigned*)(st + ST_BLO + ob + 16);
            }
#pragma unroll
            for (int mt = 0; mt < 2; mt++)
#pragma unroll
                for (int nt = 0; nt < 4; nt++) {
                    mma16816(acc[mt][nt], ahi[mt], bhi[nt]);
                    mma16816(acc[mt][nt], ahi[mt], blo[nt]);
                    mma16816(acc[mt][nt], alo[mt], bhi[nt]);
                }
        }
        __syncthreads();
    }

#pragma unroll
    for (int mt = 0; mt < 2; mt++) {
#pragma unroll
        for (int nt = 0; nt < 4; nt++) {
            int col = wn * 32 + nt * 8 + ((lane & 3) << 1);
#pragma unroll
            for (int h = 0; h < 2; h++) {
                int row = bm + wm * 32 + mt * 16 + lr + h * 8;
                size_t o = (size_t)row * C_ + col;
                float v0 = acc[mt][nt][h * 2 + 0] + Res[o];
                float v1 = acc[mt][nt][h * 2 + 1] + Res[o + 1];
                if (Res2) { v0 += Res2[o]; v1 += Res2[o + 1]; }
                *(float2*)(Out + o) = make_float2(v0, v1);
            }
        }
    }
}

// ---------------- generic fp32 GEMM with fused mix prologue / transposed epilogue ----------------
// out = ep(mix(A) @ B) * Mul + Res ; ep: 0=none,1=sigmoid,2=relu^2
// transN: write Cm transposed as [b, col, n] (N_=4096 inner); no ep/Mul/Res in that mode.
__global__ void __launch_bounds__(256) k_gemm(
    const float* __restrict__ A, const float* __restrict__ Bm, float* __restrict__ Cm,
    const float* __restrict__ Res, const float* __restrict__ Mul,
    const float* __restrict__ mixc,
    int Md, int Nd, int Kd, int ep, int transN)
{
    __shared__ float As[16][68];
    __shared__ float Bs[16][68];
    int bm = blockIdx.x * 64;
    int bn = blockIdx.y * 64;
    int tid = threadIdx.x;
    int ar = tid >> 2, ak = (tid & 3) << 2;
    int bk = tid >> 4, bc = (tid & 15) << 2;
    int tx = (tid & 15) << 2, ty = (tid >> 4) << 2;
    float acc[4][4];
#pragma unroll
    for (int i = 0; i < 4; i++)
#pragma unroll
        for (int j = 0; j < 4; j++) acc[i][j] = 0.f;
    const float* Ap = A + (size_t)(bm + ar) * Kd + ak;
    const float* Bp = Bm + (size_t)bk * Nd + bn + bc;
    int an = (bm + ar) & (N_ - 1);           // point index within batch (row of A)
    for (int k0 = 0; k0 < Kd; k0 += 16) {
        float4 a4 = *(const float4*)(Ap + k0);
        if (mixc) {
            float4 p4 = make_float4(0.f, 0.f, 0.f, 0.f);
            if (an != 0) p4 = *(const float4*)(Ap + k0 - Kd);
            float4 mc = *(const float4*)(mixc + k0 + ak);
            a4.x = mc.x * a4.x + (1.f - mc.x) * p4.x;
            a4.y = mc.y * a4.y + (1.f - mc.y) * p4.y;
            a4.z = mc.z * a4.z + (1.f - mc.z) * p4.z;
            a4.w = mc.w * a4.w + (1.f - mc.w) * p4.w;
        }
        float4 b4 = *(const float4*)(Bp + (size_t)k0 * Nd);
        __syncthreads();
        As[ak + 0][ar] = a4.x; As[ak + 1][ar] = a4.y;
        As[ak + 2][ar] = a4.z; As[ak + 3][ar] = a4.w;
        *(float4*)&Bs[bk][bc] = b4;
        __syncthreads();
#pragma unroll
        for (int kk = 0; kk < 16; kk++) {
            float4 av = *(const float4*)&As[kk][ty];
            float4 bv = *(const float4*)&Bs[kk][tx];
            float a0 = av.x, a1 = av.y, a2 = av.z, a3 = av.w;
            float b0 = bv.x, b1 = bv.y, b2 = bv.z, b3 = bv.w;
            acc[0][0] = fmaf(a0, b0, acc[0][0]); acc[0][1] = fmaf(a0, b1, acc[0][1]);
            acc[0][2] = fmaf(a0, b2, acc[0][2]); acc[0][3] = fmaf(a0, b3, acc[0][3]);
            acc[1][0] = fmaf(a1, b0, acc[1][0]); acc[1][1] = fmaf(a1, b1, acc[1][1]);
            acc[1][2] = fmaf(a1, b2, acc[1][2]); acc[1][3] = fmaf(a1, b3, acc[1][3]);
            acc[2][0] = fmaf(a2, b0, acc[2][0]); acc[2][1] = fmaf(a2, b1, acc[2][1]);
            acc[2][2] = fmaf(a2, b2, acc[2][2]); acc[2][3] = fmaf(a2, b3, acc[2][3]);
            acc[3][0] = fmaf(a3, b0, acc[3][0]); acc[3][1] = fmaf(a3, b1, acc[3][1]);
            acc[3][2] = fmaf(a3, b2, acc[3][2]); acc[3][3] = fmaf(a3, b3, acc[3][3]);
        }
    }
    if (transN) {
        int grow = bm + ty;                   // 4 consecutive rows, aligned 4
        int b = grow >> 12, n = grow & (N_ - 1);
#pragma unroll
        for (int j = 0; j < 4; j++) {
            int col = bn + tx + j;
            float4 v = make_float4(acc[0][j], acc[1][j], acc[2][j], acc[3][j]);
            *(float4*)(Cm + ((size_t)(b * C_ + col)) * N_ + n) = v;
        }
        return;
    }
#pragma unroll
    for (int i = 0; i < 4; i++) {
        size_t row = (size_t)(bm + ty + i);
#pragma unroll
        for (int j = 0; j < 4; j++) {
            size_t idx = row * Nd + bn + tx + j;
            float v = acc[i][j];
            if (ep == 1) v = 1.0f / (1.0f + __expf(-v));
            else if (ep == 2) { v = fmaxf(v, 0.f); v = v * v; }
            if (Mul) v *= Mul[idx];
            if (Res) v += Res[idx];
            Cm[idx] = v;
        }
    }
}

// ---------------- LayerNorm over last dim (C=128) ----------------
__global__ void __launch_bounds__(128) k_ln(const float* __restrict__ X,
                                            const float* __restrict__ g,
                                            const float* __restrict__ bb,
                                            float* __restrict__ Y) {
    int m = blockIdx.x, c = threadIdx.x;
    float v = X[(size_t)m * C_ + c];
    float s = v, q = v * v;
#pragma unroll
    for (int off = 16; off >= 1; off >>= 1) {
        s += __shfl_xor_sync(0xffffffffu, s, off);
        q += __shfl_xor_sync(0xffffffffu, q, off);
    }
    __shared__ float s1[4], s2[4];
    int w = c >> 5;
    if ((c & 31) == 0) { s1[w] = s; s2[w] = q; }
    __syncthreads();
    s = s1[0] + s1[1] + s1[2] + s1[3];
    q = s2[0] + s2[1] + s2[2] + s2[3];
    float mu = s * (1.0f / C_);
    float var = q * (1.0f / C_) - mu * mu;
    Y[(size_t)m * C_ + c] = (v - mu) * rsqrtf(var + 1e-5f) * g[c] + bb[c];
}

// ---------------- transpose [b,n,c] -> [b,c,n] (for y output) ----------------
__global__ void k_transpose(const float* __restrict__ in, float* __restrict__ out) {
    __shared__ float t[32][33];
    int b = blockIdx.z;
    int n0 = blockIdx.x * 32, c0 = blockIdx.y * 32;
    int x = threadIdx.x, y = threadIdx.y;   // 32 x 8
    for (int i = y; i < 32; i += 8)
        t[i][x] = in[((size_t)(b * N_ + n0 + i)) * C_ + c0 + x];
    __syncthreads();
    for (int i = y; i < 32; i += 8)
        out[((size_t)(b * C_ + c0 + i)) * N_ + n0 + x] = t[x][i];
}

// ---------------- WKV: warp per (b,c), affine chunked scan ----------------
__global__ void __launch_bounds__(256) k_wkv(
    const float* __restrict__ kT, const float* __restrict__ vT,
    const float* __restrict__ sigr,
    const float* __restrict__ td, const float* __restrict__ tf,
    float* __restrict__ out)
{
    int warp = (blockIdx.x * 256 + threadIdx.x) >> 5;
    int lane = threadIdx.x & 31;
    int b = warp >> 7, c = warp & 127;
    float w = -expf(td[c]);
    float ew = expf(w);
    float etf = expf(tf[c]);
    int n0 = lane * 128;
    const float* kp = kT + ((size_t)(b * C_ + c)) * N_ + n0;
    const float* vp = vT + ((size_t)(b * C_ + c)) * N_ + n0;
    float A = 0.f, Bv = 0.f;
#pragma unroll 4
    for (int j = 0; j < 128; j++) {
        float ek = __expf(kp[j]);
        A = fmaf(A, ew, ek * vp[j]);
        Bv = fmaf(Bv, ew, ek);
    }
    float al = __expf(128.0f * w);
    float sA = A, sB = Bv, sal = al;
#pragma unroll
    for (int off = 1; off < 32; off <<= 1) {
        float pA = __shfl_up_sync(0xffffffffu, sA, off);
        float pB = __shfl_up_sync(0xffffffffu, sB, off);
        float pal = __shfl_up_sync(0xffffffffu, sal, off);
        if (lane >= off) {
            sA = fmaf(sal, pA, sA);
            sB = fmaf(sal, pB, sB);
            sal = sal * pal;
        }
    }
    float A0 = __shfl_up_sync(0xffffffffu, sA, 1);
    float B0 = __shfl_up_sync(0xffffffffu, sB, 1);
    if (lane == 0) { A0 = 0.f; B0 = 0.f; }
    A = A0; Bv = B0;
    const float* rp = sigr + ((size_t)(b * N_ + n0)) * C_ + c;
    float* op = out + ((size_t)(b * N_ + n0)) * C_ + c;
#pragma unroll 2
    for (int j = 0; j < 128; j++) {
        float kt = kp[j], vt = vp[j];
        float ek = __expf(kt);
        float ekf = etf * ek;
        float o = (A + ekf * vt) / (Bv + ekf);
        op[(size_t)j * C_] = o * rp[(size_t)j * C_];
        A = fmaf(A, ew, ek * vt);
        Bv = fmaf(Bv, ew, ek);
    }
}

// ---------------- BN stats: deterministic two-stage (256 blocks x 32 rows) ----------------
__global__ void __launch_bounds__(128) k_bnpart(const float* __restrict__ pts) {
    int blk = blockIdx.x;
    int c = threadIdx.x;
    float s = 0.f, q = 0.f;
    int base = blk * 32;
    for (int r = 0; r < 32; r++) {
        float v = pts[(size_t)(base + r) * C_ + c];
        s += v; q = fmaf(v, v, q);
    }
    g_p1[blk * C_ + c] = s;
    g_p2[blk * C_ + c] = q;
}

__global__ void __launch_bounds__(128) k_bnred(const float* __restrict__ bg,
                                               const float* __restrict__ bb) {
    int c = threadIdx.x;
    float s = 0.f, q = 0.f;
    for (int i = 0; i < 256; i++) { s += g_p1[i * C_ + c]; q += g_p2[i * C_ + c]; }
    float mu = s * (1.0f / M_);
    float var = q * (1.0f / M_) - mu * mu;
    float a = bg[c] * rsqrtf(var + 1e-5f);
    g_bnA[c] = a;
    g_bnB[c] = bb[c] - mu * a;
}

// ---------------- head ----------------
__global__ void __launch_bounds__(256) k_head(const float* __restrict__ pts,
                                              const float* __restrict__ cw,
                                              const float* __restrict__ cb,
                                              float* __restrict__ label) {
    __shared__ float sw[CLS_ * C_];
    int tid = threadIdx.x;
    for (int i = tid; i < CLS_ * C_; i += 256) sw[i] = cw[i];
    __syncthreads();
    int m = blockIdx.x * 8 + (tid >> 5);
    int lane = tid & 31;
    float yn[4];
#pragma unroll
    for (int j = 0; j < 4; j++) {
        int c = lane + 32 * j;
        float v = fmaf(g_bnA[c], pts[(size_t)m * C_ + c], g_bnB[c]);
        yn[j] = fmaxf(v, 0.f);
    }
    int b = m >> 12, n = m & (N_ - 1);
#pragma unroll 1
    for (int d = 0; d < CLS_; d++) {
        float p = 0.f;
#pragma unroll
        for (int j = 0; j < 4; j++) p = fmaf(yn[j], sw[d * C_ + lane + 32 * j], p);
#pragma unroll
        for (int off = 16; off >= 1; off >>= 1) p += __shfl_xor_sync(0xffffffffu, p, off);
        if (lane == 0)
            label[((size_t)(b * CLS_ + d)) * N_ + n] = p + cb[d];
    }
}

// ---------------- host ----------------
extern "C" void kernel_launch(void* const* d_in, const int* in_sizes, int n_in,
                              void* d_out, int out_size) {
    const float* p        = (const float*)d_in[0];
    const float* x        = (const float*)d_in[1];
    const float* kp1_w    = (const float*)d_in[2];
    const float* kp2_w    = (const float*)d_in[3];
    const float* ln1_g    = (const float*)d_in[4];
    const float* ln1_b    = (const float*)d_in[5];
    const float* tdcy     = (const float*)d_in[6];
    const float* tfst     = (const float*)d_in[7];
    const float* mix_k    = (const float*)d_in[8];
    const float* mix_v    = (const float*)d_in[9];
    const float* mix_r    = (const float*)d_in[10];
    const float* att_wk   = (const float*)d_in[11];
    const float* att_wv   = (const float*)d_in[12];
    const float* att_wr   = (const float*)d_in[13];
    const float* att_wo   = (const float*)d_in[14];
    const float* ln2_g    = (const float*)d_in[15];
    const float* ln2_b    = (const float*)d_in[16];
    const float* cmix_k   = (const float*)d_in[17];
    const float* cmix_r   = (const float*)d_in[18];
    const float* ffn_wk   = (const float*)d_in[19];
    const float* ffn_wv   = (const float*)d_in[20];
    const float* ffn_wr   = (const float*)d_in[21];
    const float* bn_g     = (const float*)d_in[22];
    const float* bn_b     = (const float*)d_in[23];
    const float* conv_w   = (const float*)d_in[24];
    const float* conv_b   = (const float*)d_in[25];

    float* out_y = (float*)d_out;
    float* out_label = out_y + (size_t)B_ * C_ * N_;

    float *gf, *gx0, *gpts, *gxn, *grr, *gkT, *gvT, *gwkv, *gffn;
    cudaGetSymbolAddress((void**)&gf, g_f);
    cudaGetSymbolAddress((void**)&gx0, g_x0);
    cudaGetSymbolAddress((void**)&gpts, g_pts);
    cudaGetSymbolAddress((void**)&gxn, g_xn);
    cudaGetSymbolAddress((void**)&grr, g_rr);
    cudaGetSymbolAddress((void**)&gkT, g_kT);
    cudaGetSymbolAddress((void**)&gvT, g_vT);
    cudaGetSymbolAddress((void**)&gwkv, g_wkv);
    cudaGetSymbolAddress((void**)&gffn, g_ffn);

    cudaFuncSetAttribute(k_mma_kpconv, cudaFuncAttributeMaxDynamicSharedMemorySize, SM_MMA);

    dim3 tb(32, 8);
    dim3 tgrid(N_ / 32, C_ / 32, B_);
    dim3 pgrid(C_ / 32, N_ / 32, B_);

    k_init_kpts<<<1, 64>>>();
    k_prep_xyz<<<(M_ + 255) / 256, 256>>>(p);
    k_prep_feat<<<pgrid, tb>>>(x);
    k_knn<<<M_ / 8, 256>>>();

    // KPConv 1 (HMMA): f1 = fk(f0) @ w1 + f0
    k_wsplit<<<(C_ * PC_ + 255) / 256, 256>>>(kp1_w);
    k_build_fk<<<M_, 128>>>(gf);
    k_mma_kpconv<<<M_ / 64, 256, SM_MMA>>>(gf, nullptr, gf);
    // KPConv 2: pts = fk(f1) @ w2 + f1 + x0
    k_wsplit<<<(C_ * PC_ + 255) / 256, 256>>>(kp2_w);
    k_build_fk<<<M_, 128>>>(gf);
    k_mma_kpconv<<<M_ / 64, 256, SM_MMA>>>(gf, gx0, gpts);

    // ---- RWKV spatial mix (mix fused into GEMM prologue, kT/vT transposed epilogue) ----
    k_ln<<<M_, 128>>>(gpts, ln1_g, ln1_b, gxn);
    k_gemm<<<dim3(M_ / 64, C_ / 64), 256>>>(gxn, att_wk, gkT, nullptr, nullptr, mix_k, M_, C_, C_, 0, 1);
    k_gemm<<<dim3(M_ / 64, C_ / 64), 256>>>(gxn, att_wv, gvT, nullptr, nullptr, mix_v, M_, C_, C_, 0, 1);
    k_gemm<<<dim3(M_ / 64, C_ / 64), 256>>>(gxn, att_wr, grr, nullptr, nullptr, mix_r, M_, C_, C_, 1, 0);
    k_wkv<<<32, 256>>>(gkT, gvT, grr, tdcy, tfst, gwkv);
    k_gemm<<<dim3(M_ / 64, C_ / 64), 256>>>(gwkv, att_wo, gpts, gpts, nullptr, nullptr, M_, C_, C_, 0, 0);

    // ---- channel mix ----
    k_ln<<<M_, 128>>>(gpts, ln2_g, ln2_b, gxn);
    k_gemm<<<dim3(M_ / 64, F_ / 64), 256>>>(gxn, ffn_wk, gffn, nullptr, nullptr, cmix_k, M_, F_, C_, 2, 0);
    k_gemm<<<dim3(M_ / 64, C_ / 64), 256>>>(gxn, ffn_wr, grr, nullptr, nullptr, cmix_r, M_, C_, C_, 1, 0);
    k_gemm<<<dim3(M_ / 64, C_ / 64), 256>>>(gffn, ffn_wv, gpts, gpts, grr, nullptr, M_, C_, F_, 0, 0);

    // ---- outputs ----
    k_transpose<<<tgrid, tb>>>(gpts, out_y);
    k_bnpart<<<256, 128>>>(gpts);
    k_bnred<<<1, 128>>>(bn_g, bn_b);
    k_head<<<M_ / 8, 256>>>(gpts, conv_w, conv_b, out_label);
    (void)in_sizes; (void)n_in; (void)out_size;
}

// round 7
// speedup vs baseline: 3.3993x; 1.3156x over previous
#include <cuda_runtime.h>
#include <cuda_bf16.h>
#include <math.h>

static constexpr int B_ = 2, N_ = 4096, C_ = 128, K_ = 16, P_ = 43, CLS_ = 16, F_ = 512;
static constexpr int M_ = B_ * N_;
static constexpr int PC_ = P_ * C_;          // 5504
static constexpr float R2_ = 0.01f;          // RADIUS^2
static constexpr float INV_SIG_ = 10.0f;     // 1/RADIUS

// ---------------- static device scratch (no allocations) ----------------
__device__ float4 g_xyzw[M_];
__device__ int    g_nbr[M_ * K_];
__device__ float  g_kpts[P_ * 3];
__device__ float  g_f[M_ * C_];
__device__ float  g_x0[M_ * C_];
__device__ __nv_bfloat16 g_fk_hi[(size_t)M_ * PC_];   // 90 MB
__device__ __nv_bfloat16 g_fk_lo[(size_t)M_ * PC_];   // 90 MB
__device__ __nv_bfloat16 g_wT_hi[(size_t)C_ * PC_];   // kpconv weights [n][k]
__device__ __nv_bfloat16 g_wT_lo[(size_t)C_ * PC_];
// small-GEMM weights, pre-split + transposed to [n][k]
__device__ __nv_bfloat16 g_wak_hi[C_ * C_], g_wak_lo[C_ * C_];
__device__ __nv_bfloat16 g_wav_hi[C_ * C_], g_wav_lo[C_ * C_];
__device__ __nv_bfloat16 g_war_hi[C_ * C_], g_war_lo[C_ * C_];
__device__ __nv_bfloat16 g_wao_hi[C_ * C_], g_wao_lo[C_ * C_];
__device__ __nv_bfloat16 g_wfk_hi[F_ * C_], g_wfk_lo[F_ * C_];   // [512][128]
__device__ __nv_bfloat16 g_wfr_hi[C_ * C_], g_wfr_lo[C_ * C_];
__device__ __nv_bfloat16 g_wfv_hi[C_ * F_], g_wfv_lo[C_ * F_];   // [128][512]
__device__ float g_pts[M_ * C_];
__device__ float g_xn[M_ * C_];
__device__ float g_rr[M_ * C_];
__device__ float g_kT[M_ * C_];
__device__ float g_vT[M_ * C_];
__device__ float g_wkv[M_ * C_];
__device__ float g_ffn[M_ * F_];
__device__ float g_p1[256 * C_];
__device__ float g_p2[256 * C_];
__device__ float g_bnA[C_];
__device__ float g_bnB[C_];

// ---------------- helpers ----------------
__device__ __forceinline__ unsigned smem_u32(const void* p) {
    unsigned a;
    asm("{ .reg .u64 t; cvta.to.shared.u64 t, %1; cvt.u32.u64 %0, t; }" : "=r"(a) : "l"(p));
    return a;
}
__device__ __forceinline__ void cp16(void* dst, const void* src) {
    unsigned d;
    asm("{ .reg .u64 t; cvta.to.shared.u64 t, %1; cvt.u32.u64 %0, t; }" : "=r"(d) : "l"(dst));
    asm volatile("cp.async.cg.shared.global [%0], [%1], 16;" :: "r"(d), "l"(src));
}
__device__ __forceinline__ void cp_commit() {
    asm volatile("cp.async.commit_group;" ::: "memory");
}
template <int N>
__device__ __forceinline__ void cp_wait() {
    asm volatile("cp.async.wait_group %0;" :: "n"(N) : "memory");
}
__device__ __forceinline__ void mma16816(float* c, const unsigned* a, const unsigned* b) {
    asm volatile(
        "mma.sync.aligned.m16n8k16.row.col.f32.bf16.bf16.f32 "
        "{%0,%1,%2,%3}, {%4,%5,%6,%7}, {%8,%9}, {%0,%1,%2,%3};"
        : "+f"(c[0]), "+f"(c[1]), "+f"(c[2]), "+f"(c[3])
        : "r"(a[0]), "r"(a[1]), "r"(a[2]), "r"(a[3]), "r"(b[0]), "r"(b[1]));
}
__device__ __forceinline__ void ldsm4(unsigned* r, unsigned a) {
    asm volatile("ldmatrix.sync.aligned.m8n8.x4.shared.b16 {%0,%1,%2,%3}, [%4];"
        : "=r"(r[0]), "=r"(r[1]), "=r"(r[2]), "=r"(r[3]) : "r"(a));
}
__device__ __forceinline__ unsigned pack_bf2(float a, float b) {
    __nv_bfloat162 h;
    h.x = __float2bfloat16(a); h.y = __float2bfloat16(b);
    return *reinterpret_cast<unsigned*>(&h);
}

// ---------------- kernel points ----------------
__global__ void k_init_kpts() {
    int t = threadIdx.x;
    if (t >= P_) return;
    double x = 0.0, y = 0.0, z = 0.0;
    if (t > 0) {
        int mc = (t <= 14) ? 14 : 28;
        double scale = (t <= 14) ? 0.05 : 0.1;
        int i0 = (t <= 14) ? (t - 1) : (t - 15);
        double i = i0 + 0.5;
        double phi = acos(1.0 - 2.0 * i / (double)mc);
        double theta = 3.141592653589793 * (1.0 + sqrt(5.0)) * i;
        x = cos(theta) * sin(phi) * scale;
        y = sin(theta) * sin(phi) * scale;
        z = cos(phi) * scale;
    }
    g_kpts[t * 3 + 0] = (float)x;
    g_kpts[t * 3 + 1] = (float)y;
    g_kpts[t * 3 + 2] = (float)z;
}

// ---------------- prep ----------------
__global__ void k_prep_xyz(const float* __restrict__ p) {
    int m = blockIdx.x * blockDim.x + threadIdx.x;
    if (m >= M_) return;
    int b = m / N_, n = m - b * N_;
    float x = p[((size_t)b * 3 + 0) * N_ + n];
    float y = p[((size_t)b * 3 + 1) * N_ + n];
    float z = p[((size_t)b * 3 + 2) * N_ + n];
    g_xyzw[m] = make_float4(x, y, z, fmaf(x, x, fmaf(y, y, z * z)));
}

__global__ void k_prep_feat(const float* __restrict__ x) {
    __shared__ float t[32][33];
    int b = blockIdx.z;
    int c0 = blockIdx.x * 32, n0 = blockIdx.y * 32;
    int tx = threadIdx.x, ty = threadIdx.y;
    for (int i = ty; i < 32; i += 8)
        t[i][tx] = x[((size_t)(b * C_ + c0 + i)) * N_ + n0 + tx];
    __syncthreads();
    for (int i = ty; i < 32; i += 8) {
        float v = t[tx][i];
        size_t o = ((size_t)(b * N_ + n0 + i)) * C_ + c0 + tx;
        g_f[o] = v;
        g_x0[o] = v;
    }
}

// ---------------- radius-limited 16-NN ----------------
__global__ void __launch_bounds__(256) k_knn() {
    int wid = threadIdx.x >> 5, lane = threadIdx.x & 31;
    int m = blockIdx.x * 8 + wid;
    int base = (m >> 12) * N_;
    float4 q = g_xyzw[m];
    float bd[K_]; int bi[K_];
#pragma unroll
    for (int k = 0; k < K_; k++) { bd[k] = 3.4e38f; bi[k] = 0x7FFFFFFF; }
    __shared__ float4 tile[1024];
    for (int t0 = 0; t0 < N_; t0 += 1024) {
        __syncthreads();
        for (int j = threadIdx.x; j < 1024; j += 256) tile[j] = g_xyzw[base + t0 + j];
        __syncthreads();
#pragma unroll 2
        for (int t = 0; t < 32; t++) {
            int j = t * 32 + lane;
            float4 c = tile[j];
            float dot = fmaf(q.x, c.x, fmaf(q.y, c.y, q.z * c.z));
            float d2 = q.w + c.w - 2.0f * dot;
            if (d2 <= R2_ && d2 < bd[K_ - 1]) {
                int idx = t0 + j;
#pragma unroll
                for (int k = K_ - 1; k >= 0; k--) {
                    float pd = (k > 0) ? bd[k - 1] : -1.0f;
                    if (pd > d2) {
                        if (k > 0) { bd[k] = bd[k - 1]; bi[k] = bi[k - 1]; }
                    } else if (bd[k] > d2) {
                        bd[k] = d2; bi[k] = idx;
                    }
                }
            }
        }
    }
    float outd = 3.4e38f; int outi = 0x7FFFFFFF;
    for (int r = 0; r < K_; r++) {
        unsigned fb = __float_as_uint(bd[0]);
        fb = (fb & 0x80000000u) ? ~fb : (fb | 0x80000000u);
        unsigned long long key = (((unsigned long long)fb) << 32) | (unsigned)bi[0];
        unsigned long long kmin = key;
#pragma unroll
        for (int off = 16; off >= 1; off >>= 1) {
            unsigned long long o = __shfl_xor_sync(0xffffffffu, kmin, off);
            if (o < kmin) kmin = o;
        }
        if (key == kmin) {
#pragma unroll
            for (int k = 0; k < K_ - 1; k++) { bd[k] = bd[k + 1]; bi[k] = bi[k + 1]; }
            bd[K_ - 1] = 3.4e38f; bi[K_ - 1] = 0x7FFFFFFF;
        }
        if (lane == r) {
            unsigned tu = (unsigned)(kmin >> 32);
            unsigned ob = (tu & 0x80000000u) ? (tu ^ 0x80000000u) : ~tu;
            outd = __uint_as_float(ob);
            outi = (int)(unsigned)(kmin & 0xffffffffu);
        }
    }
    int wi0 = __shfl_sync(0xffffffffu, outi, 0);
    if (lane < K_) {
        int sel = (outd <= R2_) ? outi : wi0;
        g_nbr[m * K_ + lane] = base + sel;
    }
}

// ---------------- build fk: 2 points/block, [p][k] infl, float4 LDS, packed stores ----------------
__global__ void __launch_bounds__(128) k_build_fk(const float* __restrict__ fin) {
    int m0 = blockIdx.x * 2;
    int tid = threadIdx.x;
    int sub = tid >> 6, t = tid & 63, c0 = t * 2;
    __shared__ float infl[2][P_][20];
    __shared__ float nx[2][K_], ny[2][K_], nz[2][K_];
    __shared__ int nidx[2][K_];
    if (tid < 2 * K_) {
        int ss = tid >> 4, kk = tid & 15;
        int nb = g_nbr[(m0 + ss) * K_ + kk];
        nidx[ss][kk] = nb;
        float4 nq = g_xyzw[nb];
        nx[ss][kk] = nq.x; ny[ss][kk] = nq.y; nz[ss][kk] = nq.z;
    }
    __syncthreads();
    for (int e = tid; e < 2 * P_ * K_; e += 128) {
        int ss = e / (P_ * K_);
        int rem = e - ss * P_ * K_;
        int pp = rem >> 4, k = rem & 15;
        float4 cq = g_xyzw[m0 + ss];
        float rx = nx[ss][k] - cq.x, ry = ny[ss][k] - cq.y, rz = nz[ss][k] - cq.z;
        float dx = rx - g_kpts[pp * 3], dy = ry - g_kpts[pp * 3 + 1], dz = rz - g_kpts[pp * 3 + 2];
        float d = sqrtf(fmaf(dx, dx, fmaf(dy, dy, dz * dz)) + 1e-12f);
        infl[ss][pp][k] = fmaxf(0.0f, 1.0f - d * INV_SIG_);
    }
    __syncthreads();
    float2 Fv[K_];
#pragma unroll
    for (int k = 0; k < K_; k++)
        Fv[k] = *(const float2*)(fin + (size_t)nidx[sub][k] * C_ + c0);
    size_t dstb = (size_t)(m0 + sub) * PC_ + c0;
#pragma unroll 1
    for (int pp = 0; pp < P_; pp++) {
        float a0 = 0.f, a1 = 0.f;
#pragma unroll
        for (int k4 = 0; k4 < 4; k4++) {
            float4 w = *(const float4*)&infl[sub][pp][k4 * 4];
            a0 = fmaf(w.x, Fv[k4 * 4 + 0].x, a0); a1 = fmaf(w.x, Fv[k4 * 4 + 0].y, a1);
            a0 = fmaf(w.y, Fv[k4 * 4 + 1].x, a0); a1 = fmaf(w.y, Fv[k4 * 4 + 1].y, a1);
            a0 = fmaf(w.z, Fv[k4 * 4 + 2].x, a0); a1 = fmaf(w.z, Fv[k4 * 4 + 2].y, a1);
            a0 = fmaf(w.w, Fv[k4 * 4 + 3].x, a0); a1 = fmaf(w.w, Fv[k4 * 4 + 3].y, a1);
        }
        float h0 = __bfloat162float(__float2bfloat16(a0));
        float h1 = __bfloat162float(__float2bfloat16(a1));
        size_t o = dstb + (size_t)pp * C_;
        *reinterpret_cast<unsigned*>(g_fk_hi + o) = pack_bf2(a0, a1);
        *reinterpret_cast<unsigned*>(g_fk_lo + o) = pack_bf2(a0 - h0, a1 - h1);
    }
}

// ---------------- generic weight split+transpose: src[K][N] -> hi/lo [N][K] ----------------
__global__ void k_wsplitT(const float* __restrict__ src, __nv_bfloat16* __restrict__ hi,
                          __nv_bfloat16* __restrict__ lo, int Kd, int Nd) {
    int i = blockIdx.x * 256 + threadIdx.x;
    if (i >= Kd * Nd) return;
    int n = i / Kd, k = i - n * Kd;
    float v = src[(size_t)k * Nd + n];
    __nv_bfloat16 h = __float2bfloat16(v);
    hi[i] = h;
    lo[i] = __float2bfloat16(v - __bfloat162float(h));
}

// ---------------- HMMA KPConv GEMM: BM=64 BN=128 BK=64, ldmatrix fragments ----------------
static constexpr int GBK = 64;
static constexpr int NCH_ = PC_ / GBK;       // 86
static constexpr int AP = 72;                // smem row pitch (bf16 elems)
static constexpr int ST_ALO = 64 * AP * 2;               // 9216
static constexpr int ST_BHI = 2 * ST_ALO;                // 18432
static constexpr int ST_BLO = ST_BHI + 128 * AP * 2;     // 36864
static constexpr int ST_SZ  = ST_BLO + 128 * AP * 2;     // 55296
static constexpr int SM_MMA = 2 * ST_SZ;                 // 110592

__global__ void __launch_bounds__(256) k_mma_kpconv(
    const float* __restrict__ Res, const float* __restrict__ Res2, float* __restrict__ Out)
{
    extern __shared__ char smem[];
    unsigned sb = smem_u32(smem);
    int tid = threadIdx.x;
    int bm = blockIdx.x * 64;
    int wid = tid >> 5, lane = tid & 31;
    int wm = wid & 1, wn = wid >> 1;
    int li = lane & 7, lm2 = lane >> 3;
    // ldmatrix address components
    int a_m = (lm2 & 1) * 8 + li, a_k = (lm2 >> 1) * 8;
    int b_n = (lm2 >> 1) * 8 + li, b_k = (lm2 & 1) * 8;

    float acc[2][4][4];
#pragma unroll
    for (int i = 0; i < 2; i++)
#pragma unroll
        for (int j = 0; j < 4; j++)
#pragma unroll
            for (int q = 0; q < 4; q++) acc[i][j][q] = 0.f;

    auto load_chunk = [&](int ch, int s) {
        int k0 = ch * GBK;
        char* st = smem + s * ST_SZ;
#pragma unroll
        for (int i = 0; i < 2; i++) {             // A: 64 rows x 8 segs
            int idx = tid + i * 256;
            int row = idx >> 3, seg = idx & 7;
            size_t srcoff = (size_t)(bm + row) * PC_ + k0 + seg * 8;
            int dst = (row * AP + seg * 8) * 2;
            cp16(st + dst, g_fk_hi + srcoff);
            cp16(st + ST_ALO + dst, g_fk_lo + srcoff);
        }
#pragma unroll
        for (int i = 0; i < 4; i++) {             // B: 128 rows x 8 segs
            int idx = tid + i * 256;
            int row = idx >> 3, seg = idx & 7;
            size_t srcoff = (size_t)row * PC_ + k0 + seg * 8;
            int dst = (row * AP + seg * 8) * 2;
            cp16(st + ST_BHI + dst, g_wT_hi + srcoff);
            cp16(st + ST_BLO + dst, g_wT_lo + srcoff);
        }
        cp_commit();
    };

    load_chunk(0, 0);
    for (int ch = 0; ch < NCH_; ch++) {
        int s = ch & 1;
        if (ch + 1 < NCH_) { load_chunk(ch + 1, s ^ 1); cp_wait<1>(); }
        else cp_wait<0>();
        __syncthreads();
        unsigned stb = sb + s * ST_SZ;
#pragma unroll
        for (int ks = 0; ks < 4; ks++) {
            int kb = ks * 16;
            unsigned ahi[2][4], alo[2][4], bhi[2][4], blo[2][4];
#pragma unroll
            for (int mt = 0; mt < 2; mt++) {
                unsigned ad = stb + (((wm * 32 + mt * 16 + a_m) * AP) + kb + a_k) * 2;
                ldsm4(ahi[mt], ad);
                ldsm4(alo[mt], ad + ST_ALO);
            }
#pragma unroll
            for (int np = 0; np < 2; np++) {
                unsigned bdadr = stb + ST_BHI + (((wn * 32 + np * 16 + b_n) * AP) + kb + b_k) * 2;
                ldsm4(bhi[np], bdadr);
                ldsm4(blo[np], bdadr + (ST_BLO - ST_BHI));
            }
#pragma unroll
            for (int mt = 0; mt < 2; mt++)
#pragma unroll
                for (int nt = 0; nt < 4; nt++) {
                    const unsigned* bh = &bhi[nt >> 1][(nt & 1) * 2];
                    const unsigned* bl = &blo[nt >> 1][(nt & 1) * 2];
                    mma16816(acc[mt][nt], ahi[mt], bh);
                    mma16816(acc[mt][nt], ahi[mt], bl);
                    mma16816(acc[mt][nt], alo[mt], bh);
                }
        }
        __syncthreads();
    }

    int lr = lane >> 2;
#pragma unroll
    for (int mt = 0; mt < 2; mt++) {
#pragma unroll
        for (int nt = 0; nt < 4; nt++) {
            int col = wn * 32 + nt * 8 + ((lane & 3) << 1);
#pragma unroll
            for (int h = 0; h < 2; h++) {
                int row = bm + wm * 32 + mt * 16 + lr + h * 8;
                size_t o = (size_t)row * C_ + col;
                float v0 = acc[mt][nt][h * 2 + 0] + Res[o];
                float v1 = acc[mt][nt][h * 2 + 1] + Res[o + 1];
                if (Res2) { v0 += Res2[o]; v1 += Res2[o + 1]; }
                *(float2*)(Out + o) = make_float2(v0, v1);
            }
        }
    }
}

// ---------------- HMMA small GEMM: A fp32 (split on the fly), B pre-split [n][k] ----------------
// BM=64, BN=64, BK=32, 256 threads. out = ep(mix(A) @ B^T) * Mul + Res; transN bounce.
static constexpr int HP = 40;
static constexpr int H_ALO = 64 * HP * 2;      // 5120
static constexpr int H_BHI = 2 * H_ALO;        // 10240
static constexpr int H_BLO = 3 * H_ALO;        // 15360
static constexpr int H_SZ  = 4 * H_ALO;        // 20480 (>= 64*65*4 bounce)

__global__ void __launch_bounds__(256) k_hgemm(
    const float* __restrict__ A,
    const __nv_bfloat16* __restrict__ BhiT, const __nv_bfloat16* __restrict__ BloT,
    float* __restrict__ Cm, const float* __restrict__ Res, const float* __restrict__ Mul,
    const float* __restrict__ mixc, int Kd, int NdOut, int ep, int transN)
{
    extern __shared__ char smem[];
    unsigned sb = smem_u32(smem);
    int tid = threadIdx.x;
    int bm = blockIdx.x * 64, bn = blockIdx.y * 64;
    int wid = tid >> 5, lane = tid & 31;
    int wm = wid & 3, wn = wid >> 2;
    int li = lane & 7, lm2 = lane >> 3;
    int a_m = (lm2 & 1) * 8 + li, a_k = (lm2 >> 1) * 8;
    int b_n = (lm2 >> 1) * 8 + li, b_k = (lm2 & 1) * 8;

    int arow = tid >> 2, akc = (tid & 3) * 8;       // A: row 0..63, k-col {0,8,16,24}
    int an = (bm + arow) & (N_ - 1);
    int brow = tid >> 2, bseg = tid & 3;            // B: row 0..63, seg {0..3}

    float acc[4][4];
#pragma unroll
    for (int j = 0; j < 4; j++)
#pragma unroll
        for (int q = 0; q < 4; q++) acc[j][q] = 0.f;

    int nch = Kd / 32;
    for (int ch = 0; ch < nch; ch++) {
        int k0 = ch * 32;
        __syncthreads();
        // B tiles via cp.async
        {
            size_t srcoff = (size_t)(bn + brow) * Kd + k0 + bseg * 8;
            int dst = (brow * HP + bseg * 8) * 2;
            cp16(smem + H_BHI + dst, BhiT + srcoff);
            cp16(smem + H_BLO + dst, BloT + srcoff);
            cp_commit();
        }
        // A fp32 -> split bf16
        {
            const float* ap = A + (size_t)(bm + arow) * Kd + k0 + akc;
            float4 v0 = *(const float4*)ap;
            float4 v1 = *(const float4*)(ap + 4);
            if (mixc) {
                float4 p0 = make_float4(0.f, 0.f, 0.f, 0.f), p1 = p0;
                if (an != 0) {
                    p0 = *(const float4*)(ap - Kd);
                    p1 = *(const float4*)(ap - Kd + 4);
                }
                float4 m0 = *(const float4*)(mixc + k0 + akc);
                float4 m1 = *(const float4*)(mixc + k0 + akc + 4);
                v0.x = m0.x * v0.x + (1.f - m0.x) * p0.x;
                v0.y = m0.y * v0.y + (1.f - m0.y) * p0.y;
                v0.z = m0.z * v0.z + (1.f - m0.z) * p0.z;
                v0.w = m0.w * v0.w + (1.f - m0.w) * p0.w;
                v1.x = m1.x * v1.x + (1.f - m1.x) * p1.x;
                v1.y = m1.y * v1.y + (1.f - m1.y) * p1.y;
                v1.z = m1.z * v1.z + (1.f - m1.z) * p1.z;
                v1.w = m1.w * v1.w + (1.f - m1.w) * p1.w;
            }
            float f[8] = { v0.x, v0.y, v0.z, v0.w, v1.x, v1.y, v1.z, v1.w };
            uint4 hi4, lo4;
            unsigned* hp = (unsigned*)&hi4;
            unsigned* lp = (unsigned*)&lo4;
#pragma unroll
            for (int j = 0; j < 4; j++) {
                float h0 = __bfloat162float(__float2bfloat16(f[2 * j]));
                float h1 = __bfloat162float(__float2bfloat16(f[2 * j + 1]));
                hp[j] = pack_bf2(f[2 * j], f[2 * j + 1]);
                lp[j] = pack_bf2(f[2 * j] - h0, f[2 * j + 1] - h1);
            }
            int dst = (arow * HP + akc) * 2;
            *(uint4*)(smem + dst) = hi4;
            *(uint4*)(smem + H_ALO + dst) = lo4;
        }
        cp_wait<0>();
        __syncthreads();
#pragma unroll
        for (int ks = 0; ks < 2; ks++) {
            int kb = ks * 16;
            unsigned ahi[4], alo[4], bhi[2][4], blo[2][4];
            unsigned ad = sb + (((wm * 16 + a_m) * HP) + kb + a_k) * 2;
            ldsm4(ahi, ad);
            ldsm4(alo, ad + H_ALO);
#pragma unroll
            for (int np = 0; np < 2; np++) {
                unsigned bdadr = sb + H_BHI + (((wn * 32 + np * 16 + b_n) * HP) + kb + b_k) * 2;
                ldsm4(bhi[np], bdadr);
                ldsm4(blo[np], bdadr + (H_BLO - H_BHI));
            }
#pragma unroll
            for (int nt = 0; nt < 4; nt++) {
                const unsigned* bh = &bhi[nt >> 1][(nt & 1) * 2];
                const unsigned* bl = &blo[nt >> 1][(nt & 1) * 2];
                mma16816(acc[nt], ahi, bh);
                mma16816(acc[nt], ahi, bl);
                mma16816(acc[nt], alo, bh);
            }
        }
    }

    int lr = lane >> 2, lc = (lane & 3) << 1;
    if (transN) {
        __syncthreads();
        float* smf = (float*)smem;                 // [64][65]
#pragma unroll
        for (int nt = 0; nt < 4; nt++) {
            int col = wn * 32 + nt * 8 + lc;
#pragma unroll
            for (int h = 0; h < 2; h++) {
                int row = wm * 16 + lr + h * 8;
                smf[row * 65 + col]     = acc[nt][h * 2 + 0];
                smf[row * 65 + col + 1] = acc[nt][h * 2 + 1];
            }
        }
        __syncthreads();
        int row = tid & 63, cgrp = tid >> 6;
        int grow = bm + row;
        int b = grow >> 12, n = grow & (N_ - 1);
#pragma unroll
        for (int cc = cgrp * 16; cc < cgrp * 16 + 16; cc++)
            Cm[((size_t)(b * C_ + bn + cc)) * N_ + n] = smf[row * 65 + cc];
        return;
    }
#pragma unroll
    for (int nt = 0; nt < 4; nt++) {
        int col = bn + wn * 32 + nt * 8 + lc;
#pragma unroll
        for (int h = 0; h < 2; h++) {
            int row = bm + wm * 16 + lr + h * 8;
            size_t o = (size_t)row * NdOut + col;
            float v0 = acc[nt][h * 2 + 0];
            float v1 = acc[nt][h * 2 + 1];
            if (ep == 1) {
                v0 = 1.0f / (1.0f + __expf(-v0));
                v1 = 1.0f / (1.0f + __expf(-v1));
            } else if (ep == 2) {
                v0 = fmaxf(v0, 0.f); v0 = v0 * v0;
                v1 = fmaxf(v1, 0.f); v1 = v1 * v1;
            }
            if (Mul) { v0 *= Mul[o]; v1 *= Mul[o + 1]; }
            if (Res) { v0 += Res[o]; v1 += Res[o + 1]; }
            *(float2*)(Cm + o) = make_float2(v0, v1);
        }
    }
}

// ---------------- LayerNorm ----------------
__global__ void __launch_bounds__(128) k_ln(const float* __restrict__ X,
                                            const float* __restrict__ g,
                                            const float* __restrict__ bb,
                                            float* __restrict__ Y) {
    int m = blockIdx.x, c = threadIdx.x;
    float v = X[(size_t)m * C_ + c];
    float s = v, q = v * v;
#pragma unroll
    for (int off = 16; off >= 1; off >>= 1) {
        s += __shfl_xor_sync(0xffffffffu, s, off);
        q += __shfl_xor_sync(0xffffffffu, q, off);
    }
    __shared__ float s1[4], s2[4];
    int w = c >> 5;
    if ((c & 31) == 0) { s1[w] = s; s2[w] = q; }
    __syncthreads();
    s = s1[0] + s1[1] + s1[2] + s1[3];
    q = s2[0] + s2[1] + s2[2] + s2[3];
    float mu = s * (1.0f / C_);
    float var = q * (1.0f / C_) - mu * mu;
    Y[(size_t)m * C_ + c] = (v - mu) * rsqrtf(var + 1e-5f) * g[c] + bb[c];
}

// ---------------- transpose [b,n,c] -> [b,c,n] ----------------
__global__ void k_transpose(const float* __restrict__ in, float* __restrict__ out) {
    __shared__ float t[32][33];
    int b = blockIdx.z;
    int n0 = blockIdx.x * 32, c0 = blockIdx.y * 32;
    int x = threadIdx.x, y = threadIdx.y;
    for (int i = y; i < 32; i += 8)
        t[i][x] = in[((size_t)(b * N_ + n0 + i)) * C_ + c0 + x];
    __syncthreads();
    for (int i = y; i < 32; i += 8)
        out[((size_t)(b * C_ + c0 + i)) * N_ + n0 + x] = t[x][i];
}

// ---------------- WKV ----------------
__global__ void __launch_bounds__(256) k_wkv(
    const float* __restrict__ kT, const float* __restrict__ vT,
    const float* __restrict__ sigr,
    const float* __restrict__ td, const float* __restrict__ tf,
    float* __restrict__ out)
{
    int warp = (blockIdx.x * 256 + threadIdx.x) >> 5;
    int lane = threadIdx.x & 31;
    int b = warp >> 7, c = warp & 127;
    float w = -expf(td[c]);
    float ew = expf(w);
    float etf = expf(tf[c]);
    int n0 = lane * 128;
    const float* kp = kT + ((size_t)(b * C_ + c)) * N_ + n0;
    const float* vp = vT + ((size_t)(b * C_ + c)) * N_ + n0;
    float A = 0.f, Bv = 0.f;
#pragma unroll 4
    for (int j = 0; j < 128; j++) {
        float ek = __expf(kp[j]);
        A = fmaf(A, ew, ek * vp[j]);
        Bv = fmaf(Bv, ew, ek);
    }
    float al = __expf(128.0f * w);
    float sA = A, sB = Bv, sal = al;
#pragma unroll
    for (int off = 1; off < 32; off <<= 1) {
        float pA = __shfl_up_sync(0xffffffffu, sA, off);
        float pB = __shfl_up_sync(0xffffffffu, sB, off);
        float pal = __shfl_up_sync(0xffffffffu, sal, off);
        if (lane >= off) {
            sA = fmaf(sal, pA, sA);
            sB = fmaf(sal, pB, sB);
            sal = sal * pal;
        }
    }
    float A0 = __shfl_up_sync(0xffffffffu, sA, 1);
    float B0 = __shfl_up_sync(0xffffffffu, sB, 1);
    if (lane == 0) { A0 = 0.f; B0 = 0.f; }
    A = A0; Bv = B0;
    const float* rp = sigr + ((size_t)(b * N_ + n0)) * C_ + c;
    float* op = out + ((size_t)(b * N_ + n0)) * C_ + c;
#pragma unroll 2
    for (int j = 0; j < 128; j++) {
        float kt = kp[j], vt = vp[j];
        float ek = __expf(kt);
        float ekf = etf * ek;
        float o = (A + ekf * vt) / (Bv + ekf);
        op[(size_t)j * C_] = o * rp[(size_t)j * C_];
        A = fmaf(A, ew, ek * vt);
        Bv = fmaf(Bv, ew, ek);
    }
}

// ---------------- BN stats + head ----------------
__global__ void __launch_bounds__(128) k_bnpart(const float* __restrict__ pts) {
    int blk = blockIdx.x;
    int c = threadIdx.x;
    float s = 0.f, q = 0.f;
    int base = blk * 32;
    for (int r = 0; r < 32; r++) {
        float v = pts[(size_t)(base + r) * C_ + c];
        s += v; q = fmaf(v, v, q);
    }
    g_p1[blk * C_ + c] = s;
    g_p2[blk * C_ + c] = q;
}

__global__ void __launch_bounds__(128) k_bnred(const float* __restrict__ bg,
                                               const float* __restrict__ bb) {
    int c = threadIdx.x;
    float s = 0.f, q = 0.f;
    for (int i = 0; i < 256; i++) { s += g_p1[i * C_ + c]; q += g_p2[i * C_ + c]; }
    float mu = s * (1.0f / M_);
    float var = q * (1.0f / M_) - mu * mu;
    float a = bg[c] * rsqrtf(var + 1e-5f);
    g_bnA[c] = a;
    g_bnB[c] = bb[c] - mu * a;
}

__global__ void __launch_bounds__(256) k_head(const float* __restrict__ pts,
                                              const float* __restrict__ cw,
                                              const float* __restrict__ cb,
                                              float* __restrict__ label) {
    __shared__ float sw[CLS_ * C_];
    int tid = threadIdx.x;
    for (int i = tid; i < CLS_ * C_; i += 256) sw[i] = cw[i];
    __syncthreads();
    int m = blockIdx.x * 8 + (tid >> 5);
    int lane = tid & 31;
    float yn[4];
#pragma unroll
    for (int j = 0; j < 4; j++) {
        int c = lane + 32 * j;
        float v = fmaf(g_bnA[c], pts[(size_t)m * C_ + c], g_bnB[c]);
        yn[j] = fmaxf(v, 0.f);
    }
    int b = m >> 12, n = m & (N_ - 1);
#pragma unroll 1
    for (int d = 0; d < CLS_; d++) {
        float p = 0.f;
#pragma unroll
        for (int j = 0; j < 4; j++) p = fmaf(yn[j], sw[d * C_ + lane + 32 * j], p);
#pragma unroll
        for (int off = 16; off >= 1; off >>= 1) p += __shfl_xor_sync(0xffffffffu, p, off);
        if (lane == 0)
            label[((size_t)(b * CLS_ + d)) * N_ + n] = p + cb[d];
    }
}

// ---------------- host ----------------
extern "C" void kernel_launch(void* const* d_in, const int* in_sizes, int n_in,
                              void* d_out, int out_size) {
    const float* p        = (const float*)d_in[0];
    const float* x        = (const float*)d_in[1];
    const float* kp1_w    = (const float*)d_in[2];
    const float* kp2_w    = (const float*)d_in[3];
    const float* ln1_g    = (const float*)d_in[4];
    const float* ln1_b    = (const float*)d_in[5];
    const float* tdcy     = (const float*)d_in[6];
    const float* tfst     = (const float*)d_in[7];
    const float* mix_k    = (const float*)d_in[8];
    const float* mix_v    = (const float*)d_in[9];
    const float* mix_r    = (const float*)d_in[10];
    const float* att_wk   = (const float*)d_in[11];
    const float* att_wv   = (const float*)d_in[12];
    const float* att_wr   = (const float*)d_in[13];
    const float* att_wo   = (const float*)d_in[14];
    const float* ln2_g    = (const float*)d_in[15];
    const float* ln2_b    = (const float*)d_in[16];
    const float* cmix_k   = (const float*)d_in[17];
    const float* cmix_r   = (const float*)d_in[18];
    const float* ffn_wk   = (const float*)d_in[19];
    const float* ffn_wv   = (const float*)d_in[20];
    const float* ffn_wr   = (const float*)d_in[21];
    const float* bn_g     = (const float*)d_in[22];
    const float* bn_b     = (const float*)d_in[23];
    const float* conv_w   = (const float*)d_in[24];
    const float* conv_b   = (const float*)d_in[25];

    float* out_y = (float*)d_out;
    float* out_label = out_y + (size_t)B_ * C_ * N_;

    float *gf, *gx0, *gpts, *gxn, *grr, *gkT, *gvT, *gwkv, *gffn;
    cudaGetSymbolAddress((void**)&gf, g_f);
    cudaGetSymbolAddress((void**)&gx0, g_x0);
    cudaGetSymbolAddress((void**)&gpts, g_pts);
    cudaGetSymbolAddress((void**)&gxn, g_xn);
    cudaGetSymbolAddress((void**)&grr, g_rr);
    cudaGetSymbolAddress((void**)&gkT, g_kT);
    cudaGetSymbolAddress((void**)&gvT, g_vT);
    cudaGetSymbolAddress((void**)&gwkv, g_wkv);
    cudaGetSymbolAddress((void**)&gffn, g_ffn);

    __nv_bfloat16 *wak_h, *wak_l, *wav_h, *wav_l, *war_h, *war_l, *wao_h, *wao_l;
    __nv_bfloat16 *wfk_h, *wfk_l, *wfr_h, *wfr_l, *wfv_h, *wfv_l, *wkp_h, *wkp_l;
    cudaGetSymbolAddress((void**)&wak_h, g_wak_hi); cudaGetSymbolAddress((void**)&wak_l, g_wak_lo);
    cudaGetSymbolAddress((void**)&wav_h, g_wav_hi); cudaGetSymbolAddress((void**)&wav_l, g_wav_lo);
    cudaGetSymbolAddress((void**)&war_h, g_war_hi); cudaGetSymbolAddress((void**)&war_l, g_war_lo);
    cudaGetSymbolAddress((void**)&wao_h, g_wao_hi); cudaGetSymbolAddress((void**)&wao_l, g_wao_lo);
    cudaGetSymbolAddress((void**)&wfk_h, g_wfk_hi); cudaGetSymbolAddress((void**)&wfk_l, g_wfk_lo);
    cudaGetSymbolAddress((void**)&wfr_h, g_wfr_hi); cudaGetSymbolAddress((void**)&wfr_l, g_wfr_lo);
    cudaGetSymbolAddress((void**)&wfv_h, g_wfv_hi); cudaGetSymbolAddress((void**)&wfv_l, g_wfv_lo);
    cudaGetSymbolAddress((void**)&wkp_h, g_wT_hi);  cudaGetSymbolAddress((void**)&wkp_l, g_wT_lo);

    cudaFuncSetAttribute(k_mma_kpconv, cudaFuncAttributeMaxDynamicSharedMemorySize, SM_MMA);
    cudaFuncSetAttribute(k_hgemm, cudaFuncAttributeMaxDynamicSharedMemorySize, H_SZ);

    dim3 tb(32, 8);
    dim3 tgrid(N_ / 32, C_ / 32, B_);
    dim3 pgrid(C_ / 32, N_ / 32, B_);

    k_init_kpts<<<1, 64>>>();
    k_prep_xyz<<<(M_ + 255) / 256, 256>>>(p);
    k_prep_feat<<<pgrid, tb>>>(x);
    // pre-split small-GEMM weights (independent of everything else)
    k_wsplitT<<<(C_ * C_ + 255) / 256, 256>>>(att_wk, wak_h, wak_l, C_, C_);
    k_wsplitT<<<(C_ * C_ + 255) / 256, 256>>>(att_wv, wav_h, wav_l, C_, C_);
    k_wsplitT<<<(C_ * C_ + 255) / 256, 256>>>(att_wr, war_h, war_l, C_, C_);
    k_wsplitT<<<(C_ * C_ + 255) / 256, 256>>>(att_wo, wao_h, wao_l, C_, C_);
    k_wsplitT<<<(C_ * F_ + 255) / 256, 256>>>(ffn_wk, wfk_h, wfk_l, C_, F_);
    k_wsplitT<<<(C_ * C_ + 255) / 256, 256>>>(ffn_wr, wfr_h, wfr_l, C_, C_);
    k_wsplitT<<<(C_ * F_ + 255) / 256, 256>>>(ffn_wv, wfv_h, wfv_l, F_, C_);
    k_knn<<<M_ / 8, 256>>>();

    // KPConv 1: f1 = fk(f0) @ w1 + f0
    k_wsplitT<<<(PC_ * C_ + 255) / 256, 256>>>(kp1_w, wkp_h, wkp_l, PC_, C_);
    k_build_fk<<<M_ / 2, 128>>>(gf);
    k_mma_kpconv<<<M_ / 64, 256, SM_MMA>>>(gf, nullptr, gf);
    // KPConv 2: pts = fk(f1) @ w2 + f1 + x0
    k_wsplitT<<<(PC_ * C_ + 255) / 256, 256>>>(kp2_w, wkp_h, wkp_l, PC_, C_);
    k_build_fk<<<M_ / 2, 128>>>(gf);
    k_mma_kpconv<<<M_ / 64, 256, SM_MMA>>>(gf, gx0, gpts);

    // ---- RWKV spatial mix ----
    k_ln<<<M_, 128>>>(gpts, ln1_g, ln1_b, gxn);
    k_hgemm<<<dim3(128, 2), 256, H_SZ>>>(gxn, wak_h, wak_l, gkT, nullptr, nullptr, mix_k, C_, C_, 0, 1);
    k_hgemm<<<dim3(128, 2), 256, H_SZ>>>(gxn, wav_h, wav_l, gvT, nullptr, nullptr, mix_v, C_, C_, 0, 1);
    k_hgemm<<<dim3(128, 2), 256, H_SZ>>>(gxn, war_h, war_l, grr, nullptr, nullptr, mix_r, C_, C_, 1, 0);
    k_wkv<<<32, 256>>>(gkT, gvT, grr, tdcy, tfst, gwkv);
    k_hgemm<<<dim3(128, 2), 256, H_SZ>>>(gwkv, wao_h, wao_l, gpts, gpts, nullptr, nullptr, C_, C_, 0, 0);

    // ---- channel mix ----
    k_ln<<<M_, 128>>>(gpts, ln2_g, ln2_b, gxn);
    k_hgemm<<<dim3(128, 8), 256, H_SZ>>>(gxn, wfk_h, wfk_l, gffn, nullptr, nullptr, cmix_k, C_, F_, 2, 0);
    k_hgemm<<<dim3(128, 2), 256, H_SZ>>>(gxn, wfr_h, wfr_l, grr, nullptr, nullptr, cmix_r, C_, C_, 1, 0);
    k_hgemm<<<dim3(128, 2), 256, H_SZ>>>(gffn, wfv_h, wfv_l, gpts, gpts, grr, nullptr, F_, C_, 0, 0);

    // ---- outputs ----
    k_transpose<<<tgrid, tb>>>(gpts, out_y);
    k_bnpart<<<256, 128>>>(gpts);
    k_bnred<<<1, 128>>>(bn_g, bn_b);
    k_head<<<M_ / 8, 256>>>(gpts, conv_w, conv_b, out_label);
    (void)in_sizes; (void)n_in; (void)out_size;
}

// round 8
// speedup vs baseline: 3.5348x; 1.0399x over previous
#include <cuda_runtime.h>
#include <cuda_bf16.h>
#include <math.h>

static constexpr int B_ = 2, N_ = 4096, C_ = 128, K_ = 16, P_ = 43, CLS_ = 16, F_ = 512;
static constexpr int M_ = B_ * N_;
static constexpr int PC_ = P_ * C_;          // 5504
static constexpr float R2_ = 0.01f;          // RADIUS^2
static constexpr float INV_SIG_ = 10.0f;     // 1/RADIUS

// ---------------- static device scratch ----------------
__device__ float4 g_xyzw[M_];
__device__ int    g_nbr[M_ * K_];
__device__ float  g_kpts[P_ * 3];
__device__ float  g_f[M_ * C_];
__device__ float  g_x0[M_ * C_];
__device__ __nv_bfloat16 g_fk_hi[(size_t)M_ * PC_];
__device__ __nv_bfloat16 g_fk_lo[(size_t)M_ * PC_];
__device__ __nv_bfloat16 g_wT1_hi[(size_t)C_ * PC_], g_wT1_lo[(size_t)C_ * PC_];
__device__ __nv_bfloat16 g_wT2_hi[(size_t)C_ * PC_], g_wT2_lo[(size_t)C_ * PC_];
__device__ __nv_bfloat16 g_wak_hi[C_ * C_], g_wak_lo[C_ * C_];
__device__ __nv_bfloat16 g_wav_hi[C_ * C_], g_wav_lo[C_ * C_];
__device__ __nv_bfloat16 g_war_hi[C_ * C_], g_war_lo[C_ * C_];
__device__ __nv_bfloat16 g_wao_hi[C_ * C_], g_wao_lo[C_ * C_];
__device__ __nv_bfloat16 g_wfk_hi[F_ * C_], g_wfk_lo[F_ * C_];
__device__ __nv_bfloat16 g_wfr_hi[C_ * C_], g_wfr_lo[C_ * C_];
__device__ __nv_bfloat16 g_wfv_hi[C_ * F_], g_wfv_lo[C_ * F_];
__device__ float g_pts[M_ * C_];
__device__ float g_xn[M_ * C_];
__device__ float g_rr[M_ * C_];
__device__ float g_kT[M_ * C_];
__device__ float g_vT[M_ * C_];
__device__ float g_wkv[M_ * C_];
__device__ float g_ffn[M_ * F_];
__device__ float g_p1[256 * C_];
__device__ float g_p2[256 * C_];
__device__ float g_bnA[C_];
__device__ float g_bnB[C_];

// ---------------- helpers ----------------
__device__ __forceinline__ unsigned smem_u32(const void* p) {
    unsigned a;
    asm("{ .reg .u64 t; cvta.to.shared.u64 t, %1; cvt.u32.u64 %0, t; }" : "=r"(a) : "l"(p));
    return a;
}
__device__ __forceinline__ void cp16(void* dst, const void* src) {
    unsigned d;
    asm("{ .reg .u64 t; cvta.to.shared.u64 t, %1; cvt.u32.u64 %0, t; }" : "=r"(d) : "l"(dst));
    asm volatile("cp.async.cg.shared.global [%0], [%1], 16;" :: "r"(d), "l"(src));
}
__device__ __forceinline__ void cp_commit() {
    asm volatile("cp.async.commit_group;" ::: "memory");
}
template <int N>
__device__ __forceinline__ void cp_wait() {
    asm volatile("cp.async.wait_group %0;" :: "n"(N) : "memory");
}
__device__ __forceinline__ void mma16816(float* c, const unsigned* a, const unsigned* b) {
    asm volatile(
        "mma.sync.aligned.m16n8k16.row.col.f32.bf16.bf16.f32 "
        "{%0,%1,%2,%3}, {%4,%5,%6,%7}, {%8,%9}, {%0,%1,%2,%3};"
        : "+f"(c[0]), "+f"(c[1]), "+f"(c[2]), "+f"(c[3])
        : "r"(a[0]), "r"(a[1]), "r"(a[2]), "r"(a[3]), "r"(b[0]), "r"(b[1]));
}
__device__ __forceinline__ void ldsm4(unsigned* r, unsigned a) {
    asm volatile("ldmatrix.sync.aligned.m8n8.x4.shared.b16 {%0,%1,%2,%3}, [%4];"
        : "=r"(r[0]), "=r"(r[1]), "=r"(r[2]), "=r"(r[3]) : "r"(a));
}
__device__ __forceinline__ unsigned pack_bf2(float a, float b) {
    __nv_bfloat162 h;
    h.x = __float2bfloat16(a); h.y = __float2bfloat16(b);
    return *reinterpret_cast<unsigned*>(&h);
}

// ---------------- setup: kpts + xyz prep + ALL weight split-transposes ----------------
// blocks [0,1584): 32x32 split-transpose tiles; 1584: kpts; [1585,1617): xyz
__global__ void __launch_bounds__(256) k_setup(
    const float* __restrict__ p,
    const float* __restrict__ kp1, const float* __restrict__ kp2,
    const float* __restrict__ awk, const float* __restrict__ awv,
    const float* __restrict__ awr, const float* __restrict__ awo,
    const float* __restrict__ fwk, const float* __restrict__ fwr,
    const float* __restrict__ fwv)
{
    int bid = blockIdx.x;
    int tid = threadIdx.x;
    if (bid < 1584) {
        const float* src; __nv_bfloat16 *hi, *lo; int Kd, Nd, lt;
        if (bid < 688)       { src = kp1; hi = g_wT1_hi; lo = g_wT1_lo; Kd = PC_; Nd = C_; lt = bid; }
        else if (bid < 1376) { src = kp2; hi = g_wT2_hi; lo = g_wT2_lo; Kd = PC_; Nd = C_; lt = bid - 688; }
        else if (bid < 1392) { src = awk; hi = g_wak_hi; lo = g_wak_lo; Kd = C_; Nd = C_; lt = bid - 1376; }
        else if (bid < 1408) { src = awv; hi = g_wav_hi; lo = g_wav_lo; Kd = C_; Nd = C_; lt = bid - 1392; }
        else if (bid < 1424) { src = awr; hi = g_war_hi; lo = g_war_lo; Kd = C_; Nd = C_; lt = bid - 1408; }
        else if (bid < 1440) { src = awo; hi = g_wao_hi; lo = g_wao_lo; Kd = C_; Nd = C_; lt = bid - 1424; }
        else if (bid < 1504) { src = fwk; hi = g_wfk_hi; lo = g_wfk_lo; Kd = C_; Nd = F_; lt = bid - 1440; }
        else if (bid < 1520) { src = fwr; hi = g_wfr_hi; lo = g_wfr_lo; Kd = C_; Nd = C_; lt = bid - 1504; }
        else                 { src = fwv; hi = g_wfv_hi; lo = g_wfv_lo; Kd = F_; Nd = C_; lt = bid - 1520; }
        int tn = Nd / 32;
        int kt = lt / tn, nt = lt - kt * tn;
        int k0 = kt * 32, n0 = nt * 32;
        __shared__ float sm[32][33];
        int tx = tid & 31, ty = tid >> 5;
        for (int i = ty; i < 32; i += 8)
            sm[i][tx] = src[(size_t)(k0 + i) * Nd + n0 + tx];
        __syncthreads();
        for (int i = ty; i < 32; i += 8) {
            float v = sm[tx][i];
            __nv_bfloat16 h = __float2bfloat16(v);
            size_t o = (size_t)(n0 + i) * Kd + k0 + tx;
            hi[o] = h;
            lo[o] = __float2bfloat16(v - __bfloat162float(h));
        }
    } else if (bid == 1584) {
        int t = tid;
        if (t < P_) {
            double x = 0.0, y = 0.0, z = 0.0;
            if (t > 0) {
                int mc = (t <= 14) ? 14 : 28;
                double scale = (t <= 14) ? 0.05 : 0.1;
                int i0 = (t <= 14) ? (t - 1) : (t - 15);
                double i = i0 + 0.5;
                double phi = acos(1.0 - 2.0 * i / (double)mc);
                double theta = 3.141592653589793 * (1.0 + sqrt(5.0)) * i;
                x = cos(theta) * sin(phi) * scale;
                y = sin(theta) * sin(phi) * scale;
                z = cos(phi) * scale;
            }
            g_kpts[t * 3 + 0] = (float)x;
            g_kpts[t * 3 + 1] = (float)y;
            g_kpts[t * 3 + 2] = (float)z;
        }
    } else {
        int m = (bid - 1585) * 256 + tid;
        int b = m / N_, n = m - b * N_;
        float x = p[((size_t)b * 3 + 0) * N_ + n];
        float y = p[((size_t)b * 3 + 1) * N_ + n];
        float z = p[((size_t)b * 3 + 2) * N_ + n];
        g_xyzw[m] = make_float4(x, y, z, fmaf(x, x, fmaf(y, y, z * z)));
    }
}

// ---------------- knn (blocks 0..1023) + feature transpose (1024..2047) ----------------
__global__ void __launch_bounds__(256) k_knn_prep(const float* __restrict__ x) {
    __shared__ float4 tile[1024];
    int tid = threadIdx.x;
    if (blockIdx.x >= 1024) {
        // prep_feat: x[b,c,n] -> g_f/g_x0 [b*n, c]
        float (*sm)[33] = reinterpret_cast<float(*)[33]>(tile);
        int pb = blockIdx.x - 1024;
        int c0 = (pb & 3) * 32, n0 = ((pb >> 2) & 127) * 32, b = pb >> 9;
        int tx = tid & 31, ty = tid >> 5;
        for (int i = ty; i < 32; i += 8)
            sm[i][tx] = x[((size_t)(b * C_ + c0 + i)) * N_ + n0 + tx];
        __syncthreads();
        for (int i = ty; i < 32; i += 8) {
            float v = sm[tx][i];
            size_t o = ((size_t)(b * N_ + n0 + i)) * C_ + c0 + tx;
            g_f[o] = v;
            g_x0[o] = v;
        }
        return;
    }
    int wid = tid >> 5, lane = tid & 31;
    int m = blockIdx.x * 8 + wid;
    int base = (m >> 12) * N_;
    float4 q = g_xyzw[m];
    float bd[K_]; int bi[K_];
#pragma unroll
    for (int k = 0; k < K_; k++) { bd[k] = 3.4e38f; bi[k] = 0x7FFFFFFF; }
    for (int t0 = 0; t0 < N_; t0 += 1024) {
        __syncthreads();
        for (int j = tid; j < 1024; j += 256) tile[j] = g_xyzw[base + t0 + j];
        __syncthreads();
#pragma unroll 2
        for (int t = 0; t < 32; t++) {
            int j = t * 32 + lane;
            float4 c = tile[j];
            float dot = fmaf(q.x, c.x, fmaf(q.y, c.y, q.z * c.z));
            float d2 = q.w + c.w - 2.0f * dot;
            if (d2 <= R2_ && d2 < bd[K_ - 1]) {
                int idx = t0 + j;
#pragma unroll
                for (int k = K_ - 1; k >= 0; k--) {
                    float pd = (k > 0) ? bd[k - 1] : -1.0f;
                    if (pd > d2) {
                        if (k > 0) { bd[k] = bd[k - 1]; bi[k] = bi[k - 1]; }
                    } else if (bd[k] > d2) {
                        bd[k] = d2; bi[k] = idx;
                    }
                }
            }
        }
    }
    float outd = 3.4e38f; int outi = 0x7FFFFFFF;
    for (int r = 0; r < K_; r++) {
        unsigned fb = __float_as_uint(bd[0]);
        fb = (fb & 0x80000000u) ? ~fb : (fb | 0x80000000u);
        unsigned long long key = (((unsigned long long)fb) << 32) | (unsigned)bi[0];
        unsigned long long kmin = key;
#pragma unroll
        for (int off = 16; off >= 1; off >>= 1) {
            unsigned long long o = __shfl_xor_sync(0xffffffffu, kmin, off);
            if (o < kmin) kmin = o;
        }
        if (key == kmin) {
#pragma unroll
            for (int k = 0; k < K_ - 1; k++) { bd[k] = bd[k + 1]; bi[k] = bi[k + 1]; }
            bd[K_ - 1] = 3.4e38f; bi[K_ - 1] = 0x7FFFFFFF;
        }
        if (lane == r) {
            unsigned tu = (unsigned)(kmin >> 32);
            unsigned ob = (tu & 0x80000000u) ? (tu ^ 0x80000000u) : ~tu;
            outd = __uint_as_float(ob);
            outi = (int)(unsigned)(kmin & 0xffffffffu);
        }
    }
    int wi0 = __shfl_sync(0xffffffffu, outi, 0);
    if (lane < K_) {
        int sel = (outd <= R2_) ? outi : wi0;
        g_nbr[m * K_ + lane] = base + sel;
    }
}

// ---------------- build fk ----------------
__global__ void __launch_bounds__(128) k_build_fk(const float* __restrict__ fin) {
    int m0 = blockIdx.x * 2;
    int tid = threadIdx.x;
    int sub = tid >> 6, t = tid & 63, c0 = t * 2;
    __shared__ float infl[2][P_][20];
    __shared__ float nx[2][K_], ny[2][K_], nz[2][K_];
    __shared__ int nidx[2][K_];
    if (tid < 2 * K_) {
        int ss = tid >> 4, kk = tid & 15;
        int nb = g_nbr[(m0 + ss) * K_ + kk];
        nidx[ss][kk] = nb;
        float4 nq = g_xyzw[nb];
        nx[ss][kk] = nq.x; ny[ss][kk] = nq.y; nz[ss][kk] = nq.z;
    }
    __syncthreads();
    for (int e = tid; e < 2 * P_ * K_; e += 128) {
        int ss = e / (P_ * K_);
        int rem = e - ss * P_ * K_;
        int pp = rem >> 4, k = rem & 15;
        float4 cq = g_xyzw[m0 + ss];
        float rx = nx[ss][k] - cq.x, ry = ny[ss][k] - cq.y, rz = nz[ss][k] - cq.z;
        float dx = rx - g_kpts[pp * 3], dy = ry - g_kpts[pp * 3 + 1], dz = rz - g_kpts[pp * 3 + 2];
        float d = sqrtf(fmaf(dx, dx, fmaf(dy, dy, dz * dz)) + 1e-12f);
        infl[ss][pp][k] = fmaxf(0.0f, 1.0f - d * INV_SIG_);
    }
    __syncthreads();
    float2 Fv[K_];
#pragma unroll
    for (int k = 0; k < K_; k++)
        Fv[k] = *(const float2*)(fin + (size_t)nidx[sub][k] * C_ + c0);
    size_t dstb = (size_t)(m0 + sub) * PC_ + c0;
#pragma unroll 1
    for (int pp = 0; pp < P_; pp++) {
        float a0 = 0.f, a1 = 0.f;
#pragma unroll
        for (int k4 = 0; k4 < 4; k4++) {
            float4 w = *(const float4*)&infl[sub][pp][k4 * 4];
            a0 = fmaf(w.x, Fv[k4 * 4 + 0].x, a0); a1 = fmaf(w.x, Fv[k4 * 4 + 0].y, a1);
            a0 = fmaf(w.y, Fv[k4 * 4 + 1].x, a0); a1 = fmaf(w.y, Fv[k4 * 4 + 1].y, a1);
            a0 = fmaf(w.z, Fv[k4 * 4 + 2].x, a0); a1 = fmaf(w.z, Fv[k4 * 4 + 2].y, a1);
            a0 = fmaf(w.w, Fv[k4 * 4 + 3].x, a0); a1 = fmaf(w.w, Fv[k4 * 4 + 3].y, a1);
        }
        float h0 = __bfloat162float(__float2bfloat16(a0));
        float h1 = __bfloat162float(__float2bfloat16(a1));
        size_t o = dstb + (size_t)pp * C_;
        *reinterpret_cast<unsigned*>(g_fk_hi + o) = pack_bf2(a0, a1);
        *reinterpret_cast<unsigned*>(g_fk_lo + o) = pack_bf2(a0 - h0, a1 - h1);
    }
}

// ---------------- HMMA KPConv GEMM: BM=64 BN=128 BK=64, 3-stage pipeline ----------------
static constexpr int GBK = 64;
static constexpr int NCH_ = PC_ / GBK;       // 86
static constexpr int AP = 72;
static constexpr int ST_ALO = 64 * AP * 2;               // 9216
static constexpr int ST_BHI = 2 * ST_ALO;                // 18432
static constexpr int ST_BLO = ST_BHI + 128 * AP * 2;     // 36864
static constexpr int ST_SZ  = ST_BLO + 128 * AP * 2;     // 55296
static constexpr int SM_MMA = 3 * ST_SZ;                 // 165888

__global__ void __launch_bounds__(256) k_mma_kpconv(
    const __nv_bfloat16* __restrict__ Bh, const __nv_bfloat16* __restrict__ Bl,
    const float* __restrict__ Res, const float* __restrict__ Res2, float* __restrict__ Out)
{
    extern __shared__ char smem[];
    unsigned sb = smem_u32(smem);
    int tid = threadIdx.x;
    int bm = blockIdx.x * 64;
    int wid = tid >> 5, lane = tid & 31;
    int wm = wid & 1, wn = wid >> 1;
    int li = lane & 7, lm2 = lane >> 3;
    int a_m = (lm2 & 1) * 8 + li, a_k = (lm2 >> 1) * 8;
    int b_n = (lm2 >> 1) * 8 + li, b_k = (lm2 & 1) * 8;

    float acc[2][4][4];
#pragma unroll
    for (int i = 0; i < 2; i++)
#pragma unroll
        for (int j = 0; j < 4; j++)
#pragma unroll
            for (int q = 0; q < 4; q++) acc[i][j][q] = 0.f;

    auto load_chunk = [&](int ch, int s) {
        int k0 = ch * GBK;
        char* st = smem + s * ST_SZ;
#pragma unroll
        for (int i = 0; i < 2; i++) {
            int idx = tid + i * 256;
            int row = idx >> 3, seg = idx & 7;
            size_t srcoff = (size_t)(bm + row) * PC_ + k0 + seg * 8;
            int dst = (row * AP + seg * 8) * 2;
            cp16(st + dst, g_fk_hi + srcoff);
            cp16(st + ST_ALO + dst, g_fk_lo + srcoff);
        }
#pragma unroll
        for (int i = 0; i < 4; i++) {
            int idx = tid + i * 256;
            int row = idx >> 3, seg = idx & 7;
            size_t srcoff = (size_t)row * PC_ + k0 + seg * 8;
            int dst = (row * AP + seg * 8) * 2;
            cp16(st + ST_BHI + dst, Bh + srcoff);
            cp16(st + ST_BLO + dst, Bl + srcoff);
        }
        cp_commit();
    };

    load_chunk(0, 0);
    load_chunk(1, 1);
    for (int ch = 0; ch < NCH_; ch++) {
        int s = ch % 3;
        if (ch + 2 < NCH_) { load_chunk(ch + 2, (ch + 2) % 3); cp_wait<2>(); }
        else if (ch + 1 < NCH_) cp_wait<1>();
        else cp_wait<0>();
        __syncthreads();
        unsigned stb = sb + s * ST_SZ;
#pragma unroll
        for (int ks = 0; ks < 4; ks++) {
            int kb = ks * 16;
            unsigned ahi[2][4], alo[2][4], bhi[2][4], blo[2][4];
#pragma unroll
            for (int mt = 0; mt < 2; mt++) {
                unsigned ad = stb + (((wm * 32 + mt * 16 + a_m) * AP) + kb + a_k) * 2;
                ldsm4(ahi[mt], ad);
                ldsm4(alo[mt], ad + ST_ALO);
            }
#pragma unroll
            for (int np = 0; np < 2; np++) {
                unsigned bdadr = stb + ST_BHI + (((wn * 32 + np * 16 + b_n) * AP) + kb + b_k) * 2;
                ldsm4(bhi[np], bdadr);
                ldsm4(blo[np], bdadr + (ST_BLO - ST_BHI));
            }
#pragma unroll
            for (int mt = 0; mt < 2; mt++)
#pragma unroll
                for (int nt = 0; nt < 4; nt++) {
                    const unsigned* bh = &bhi[nt >> 1][(nt & 1) * 2];
                    const unsigned* bl = &blo[nt >> 1][(nt & 1) * 2];
                    mma16816(acc[mt][nt], ahi[mt], bh);
                    mma16816(acc[mt][nt], ahi[mt], bl);
                    mma16816(acc[mt][nt], alo[mt], bh);
                }
        }
        __syncthreads();
    }

    int lr = lane >> 2;
#pragma unroll
    for (int mt = 0; mt < 2; mt++) {
#pragma unroll
        for (int nt = 0; nt < 4; nt++) {
            int col = wn * 32 + nt * 8 + ((lane & 3) << 1);
#pragma unroll
            for (int h = 0; h < 2; h++) {
                int row = bm + wm * 32 + mt * 16 + lr + h * 8;
                size_t o = (size_t)row * C_ + col;
                float v0 = acc[mt][nt][h * 2 + 0] + Res[o];
                float v1 = acc[mt][nt][h * 2 + 1] + Res[o + 1];
                if (Res2) { v0 += Res2[o]; v1 += Res2[o + 1]; }
                *(float2*)(Out + o) = make_float2(v0, v1);
            }
        }
    }
}

// ---------------- HMMA small GEMM, double-buffered ----------------
static constexpr int HP = 40;
static constexpr int H_STG = 20480;   // per stage: Ahi 5120 | Alo 5120 | Bhi 5120 | Blo 5120
static constexpr int H_SZ = 2 * H_STG;

__global__ void __launch_bounds__(256) k_hgemm(
    const float* __restrict__ A,
    const __nv_bfloat16* __restrict__ BhiT, const __nv_bfloat16* __restrict__ BloT,
    float* __restrict__ Cm, const float* __restrict__ Res, const float* __restrict__ Mul,
    const float* __restrict__ mixc, int Kd, int NdOut, int ep, int transN)
{
    extern __shared__ char smem[];
    unsigned sb = smem_u32(smem);
    int tid = threadIdx.x;
    int bm = blockIdx.x * 64, bn = blockIdx.y * 64;
    int wid = tid >> 5, lane = tid & 31;
    int wm = wid & 3, wn = wid >> 2;
    int li = lane & 7, lm2 = lane >> 3;
    int a_m = (lm2 & 1) * 8 + li, a_k = (lm2 >> 1) * 8;
    int b_n = (lm2 >> 1) * 8 + li, b_k = (lm2 & 1) * 8;

    int arow = tid >> 2, akc = (tid & 3) * 8;
    int an = (bm + arow) & (N_ - 1);
    int brow = tid >> 2, bseg = tid & 3;

    float acc[4][4];
#pragma unroll
    for (int j = 0; j < 4; j++)
#pragma unroll
        for (int q = 0; q < 4; q++) acc[j][q] = 0.f;

    auto loadA = [&](int k0, float* f) {
        const float* ap = A + (size_t)(bm + arow) * Kd + k0 + akc;
        float4 v0 = *(const float4*)ap;
        float4 v1 = *(const float4*)(ap + 4);
        if (mixc) {
            float4 p0 = make_float4(0.f, 0.f, 0.f, 0.f), p1 = p0;
            if (an != 0) {
                p0 = *(const float4*)(ap - Kd);
                p1 = *(const float4*)(ap - Kd + 4);
            }
            float4 m0 = *(const float4*)(mixc + k0 + akc);
            float4 m1 = *(const float4*)(mixc + k0 + akc + 4);
            v0.x = m0.x * v0.x + (1.f - m0.x) * p0.x;
            v0.y = m0.y * v0.y + (1.f - m0.y) * p0.y;
            v0.z = m0.z * v0.z + (1.f - m0.z) * p0.z;
            v0.w = m0.w * v0.w + (1.f - m0.w) * p0.w;
            v1.x = m1.x * v1.x + (1.f - m1.x) * p1.x;
            v1.y = m1.y * v1.y + (1.f - m1.y) * p1.y;
            v1.z = m1.z * v1.z + (1.f - m1.z) * p1.z;
            v1.w = m1.w * v1.w + (1.f - m1.w) * p1.w;
        }
        f[0] = v0.x; f[1] = v0.y; f[2] = v0.z; f[3] = v0.w;
        f[4] = v1.x; f[5] = v1.y; f[6] = v1.z; f[7] = v1.w;
    };
    auto storeA = [&](const float* f, int stg) {
        uint4 hi4, lo4;
        unsigned* hp = (unsigned*)&hi4;
        unsigned* lp = (unsigned*)&lo4;
#pragma unroll
        for (int j = 0; j < 4; j++) {
            float h0 = __bfloat162float(__float2bfloat16(f[2 * j]));
            float h1 = __bfloat162float(__float2bfloat16(f[2 * j + 1]));
            hp[j] = pack_bf2(f[2 * j], f[2 * j + 1]);
            lp[j] = pack_bf2(f[2 * j] - h0, f[2 * j + 1] - h1);
        }
        int dst = stg * H_STG + (arow * HP + akc) * 2;
        *(uint4*)(smem + dst) = hi4;
        *(uint4*)(smem + dst + 5120) = lo4;
    };
    auto loadB = [&](int k0, int stg) {
        size_t srcoff = (size_t)(bn + brow) * Kd + k0 + bseg * 8;
        int dst = stg * H_STG + 10240 + (brow * HP + bseg * 8) * 2;
        cp16(smem + dst, BhiT + srcoff);
        cp16(smem + dst + 5120, BloT + srcoff);
        cp_commit();
    };

    int nch = Kd / 32;
    float av[8];
    loadA(0, av);
    loadB(0, 0);
    for (int ch = 0; ch < nch; ch++) {
        int s = ch & 1;
        storeA(av, s);
        if (ch + 1 < nch) {
            loadB((ch + 1) * 32, s ^ 1);
            loadA((ch + 1) * 32, av);
            cp_wait<1>();
        } else {
            cp_wait<0>();
        }
        __syncthreads();
        unsigned base = sb + s * H_STG;
#pragma unroll
        for (int ks = 0; ks < 2; ks++) {
            int kb = ks * 16;
            unsigned ahi[4], alo[4], bhi[2][4], blo[2][4];
            unsigned ad = base + (((wm * 16 + a_m) * HP) + kb + a_k) * 2;
            ldsm4(ahi, ad);
            ldsm4(alo, ad + 5120);
#pragma unroll
            for (int np = 0; np < 2; np++) {
                unsigned bdadr = base + 10240 + (((wn * 32 + np * 16 + b_n) * HP) + kb + b_k) * 2;
                ldsm4(bhi[np], bdadr);
                ldsm4(blo[np], bdadr + 5120);
            }
#pragma unroll
            for (int nt = 0; nt < 4; nt++) {
                const unsigned* bh = &bhi[nt >> 1][(nt & 1) * 2];
                const unsigned* bl = &blo[nt >> 1][(nt & 1) * 2];
                mma16816(acc[nt], ahi, bh);
                mma16816(acc[nt], ahi, bl);
                mma16816(acc[nt], alo, bh);
            }
        }
        __syncthreads();
    }

    int lr = lane >> 2, lc = (lane & 3) << 1;
    if (transN) {
        float* smf = (float*)smem;   // [64][65] bounce, 16640 B
#pragma unroll
        for (int nt = 0; nt < 4; nt++) {
            int col = wn * 32 + nt * 8 + lc;
#pragma unroll
            for (int h = 0; h < 2; h++) {
                int row = wm * 16 + lr + h * 8;
                smf[row * 65 + col]     = acc[nt][h * 2 + 0];
                smf[row * 65 + col + 1] = acc[nt][h * 2 + 1];
            }
        }
        __syncthreads();
        int row = tid & 63, cgrp = tid >> 6;
        int grow = bm + row;
        int b = grow >> 12, n = grow & (N_ - 1);
#pragma unroll
        for (int cc = cgrp * 16; cc < cgrp * 16 + 16; cc++)
            Cm[((size_t)(b * C_ + bn + cc)) * N_ + n] = smf[row * 65 + cc];
        return;
    }
#pragma unroll
    for (int nt = 0; nt < 4; nt++) {
        int col = bn + wn * 32 + nt * 8 + lc;
#pragma unroll
        for (int h = 0; h < 2; h++) {
            int row = bm + wm * 16 + lr + h * 8;
            size_t o = (size_t)row * NdOut + col;
            float v0 = acc[nt][h * 2 + 0];
            float v1 = acc[nt][h * 2 + 1];
            if (ep == 1) {
                v0 = 1.0f / (1.0f + __expf(-v0));
                v1 = 1.0f / (1.0f + __expf(-v1));
            } else if (ep == 2) {
                v0 = fmaxf(v0, 0.f); v0 = v0 * v0;
                v1 = fmaxf(v1, 0.f); v1 = v1 * v1;
            }
            if (Mul) { v0 *= Mul[o]; v1 *= Mul[o + 1]; }
            if (Res) { v0 += Res[o]; v1 += Res[o + 1]; }
            *(float2*)(Cm + o) = make_float2(v0, v1);
        }
    }
}

// ---------------- LayerNorm ----------------
__global__ void __launch_bounds__(128) k_ln(const float* __restrict__ X,
                                            const float* __restrict__ g,
                                            const float* __restrict__ bb,
                                            float* __restrict__ Y) {
    int m = blockIdx.x, c = threadIdx.x;
    float v = X[(size_t)m * C_ + c];
    float s = v, q = v * v;
#pragma unroll
    for (int off = 16; off >= 1; off >>= 1) {
        s += __shfl_xor_sync(0xffffffffu, s, off);
        q += __shfl_xor_sync(0xffffffffu, q, off);
    }
    __shared__ float s1[4], s2[4];
    int w = c >> 5;
    if ((c & 31) == 0) { s1[w] = s; s2[w] = q; }
    __syncthreads();
    s = s1[0] + s1[1] + s1[2] + s1[3];
    q = s2[0] + s2[1] + s2[2] + s2[3];
    float mu = s * (1.0f / C_);
    float var = q * (1.0f / C_) - mu * mu;
    Y[(size_t)m * C_ + c] = (v - mu) * rsqrtf(var + 1e-5f) * g[c] + bb[c];
}

// ---------------- transpose [b,n,c] -> [b,c,n] ----------------
__global__ void k_transpose(const float* __restrict__ in, float* __restrict__ out) {
    __shared__ float t[32][33];
    int b = blockIdx.z;
    int n0 = blockIdx.x * 32, c0 = blockIdx.y * 32;
    int x = threadIdx.x, y = threadIdx.y;
    for (int i = y; i < 32; i += 8)
        t[i][x] = in[((size_t)(b * N_ + n0 + i)) * C_ + c0 + x];
    __syncthreads();
    for (int i = y; i < 32; i += 8)
        out[((size_t)(b * C_ + c0 + i)) * N_ + n0 + x] = t[x][i];
}

// ---------------- WKV ----------------
__global__ void __launch_bounds__(256) k_wkv(
    const float* __restrict__ kT, const float* __restrict__ vT,
    const float* __restrict__ sigr,
    const float* __restrict__ td, const float* __restrict__ tf,
    float* __restrict__ out)
{
    int warp = (blockIdx.x * 256 + threadIdx.x) >> 5;
    int lane = threadIdx.x & 31;
    int b = warp >> 7, c = warp & 127;
    float w = -expf(td[c]);
    float ew = expf(w);
    float etf = expf(tf[c]);
    int n0 = lane * 128;
    const float* kp = kT + ((size_t)(b * C_ + c)) * N_ + n0;
    const float* vp = vT + ((size_t)(b * C_ + c)) * N_ + n0;
    float A = 0.f, Bv = 0.f;
#pragma unroll 4
    for (int j = 0; j < 128; j++) {
        float ek = __expf(kp[j]);
        A = fmaf(A, ew, ek * vp[j]);
        Bv = fmaf(Bv, ew, ek);
    }
    float al = __expf(128.0f * w);
    float sA = A, sB = Bv, sal = al;
#pragma unroll
    for (int off = 1; off < 32; off <<= 1) {
        float pA = __shfl_up_sync(0xffffffffu, sA, off);
        float pB = __shfl_up_sync(0xffffffffu, sB, off);
        float pal = __shfl_up_sync(0xffffffffu, sal, off);
        if (lane >= off) {
            sA = fmaf(sal, pA, sA);
            sB = fmaf(sal, pB, sB);
            sal = sal * pal;
        }
    }
    float A0 = __shfl_up_sync(0xffffffffu, sA, 1);
    float B0 = __shfl_up_sync(0xffffffffu, sB, 1);
    if (lane == 0) { A0 = 0.f; B0 = 0.f; }
    A = A0; Bv = B0;
    const float* rp = sigr + ((size_t)(b * N_ + n0)) * C_ + c;
    float* op = out + ((size_t)(b * N_ + n0)) * C_ + c;
#pragma unroll 2
    for (int j = 0; j < 128; j++) {
        float kt = kp[j], vt = vp[j];
        float ek = __expf(kt);
        float ekf = etf * ek;
        float o = (A + ekf * vt) / (Bv + ekf);
        op[(size_t)j * C_] = o * rp[(size_t)j * C_];
        A = fmaf(A, ew, ek * vt);
        Bv = fmaf(Bv, ew, ek);
    }
}

// ---------------- BN stats + head ----------------
__global__ void __launch_bounds__(128) k_bnpart(const float* __restrict__ pts) {
    int blk = blockIdx.x;
    int c = threadIdx.x;
    float s = 0.f, q = 0.f;
    int base = blk * 32;
    for (int r = 0; r < 32; r++) {
        float v = pts[(size_t)(base + r) * C_ + c];
        s += v; q = fmaf(v, v, q);
    }
    g_p1[blk * C_ + c] = s;
    g_p2[blk * C_ + c] = q;
}

__global__ void __launch_bounds__(128) k_bnred(const float* __restrict__ bg,
                                               const float* __restrict__ bb) {
    int c = threadIdx.x;
    float s = 0.f, q = 0.f;
    for (int i = 0; i < 256; i++) { s += g_p1[i * C_ + c]; q += g_p2[i * C_ + c]; }
    float mu = s * (1.0f / M_);
    float var = q * (1.0f / M_) - mu * mu;
    float a = bg[c] * rsqrtf(var + 1e-5f);
    g_bnA[c] = a;
    g_bnB[c] = bb[c] - mu * a;
}

__global__ void __launch_bounds__(256) k_head(const float* __restrict__ pts,
                                              const float* __restrict__ cw,
                                              const float* __restrict__ cb,
                                              float* __restrict__ label) {
    __shared__ float sw[CLS_ * C_];
    int tid = threadIdx.x;
    for (int i = tid; i < CLS_ * C_; i += 256) sw[i] = cw[i];
    __syncthreads();
    int m = blockIdx.x * 8 + (tid >> 5);
    int lane = tid & 31;
    float yn[4];
#pragma unroll
    for (int j = 0; j < 4; j++) {
        int c = lane + 32 * j;
        float v = fmaf(g_bnA[c], pts[(size_t)m * C_ + c], g_bnB[c]);
        yn[j] = fmaxf(v, 0.f);
    }
    int b = m >> 12, n = m & (N_ - 1);
#pragma unroll 1
    for (int d = 0; d < CLS_; d++) {
        float p = 0.f;
#pragma unroll
        for (int j = 0; j < 4; j++) p = fmaf(yn[j], sw[d * C_ + lane + 32 * j], p);
#pragma unroll
        for (int off = 16; off >= 1; off >>= 1) p += __shfl_xor_sync(0xffffffffu, p, off);
        if (lane == 0)
            label[((size_t)(b * CLS_ + d)) * N_ + n] = p + cb[d];
    }
}

// ---------------- host ----------------
extern "C" void kernel_launch(void* const* d_in, const int* in_sizes, int n_in,
                              void* d_out, int out_size) {
    const float* p        = (const float*)d_in[0];
    const float* x        = (const float*)d_in[1];
    const float* kp1_w    = (const float*)d_in[2];
    const float* kp2_w    = (const float*)d_in[3];
    const float* ln1_g    = (const float*)d_in[4];
    const float* ln1_b    = (const float*)d_in[5];
    const float* tdcy     = (const float*)d_in[6];
    const float* tfst     = (const float*)d_in[7];
    const float* mix_k    = (const float*)d_in[8];
    const float* mix_v    = (const float*)d_in[9];
    const float* mix_r    = (const float*)d_in[10];
    const float* att_wk   = (const float*)d_in[11];
    const float* att_wv   = (const float*)d_in[12];
    const float* att_wr   = (const float*)d_in[13];
    const float* att_wo   = (const float*)d_in[14];
    const float* ln2_g    = (const float*)d_in[15];
    const float* ln2_b    = (const float*)d_in[16];
    const float* cmix_k   = (const float*)d_in[17];
    const float* cmix_r   = (const float*)d_in[18];
    const float* ffn_wk   = (const float*)d_in[19];
    const float* ffn_wv   = (const float*)d_in[20];
    const float* ffn_wr   = (const float*)d_in[21];
    const float* bn_g     = (const float*)d_in[22];
    const float* bn_b     = (const float*)d_in[23];
    const float* conv_w   = (const float*)d_in[24];
    const float* conv_b   = (const float*)d_in[25];

    float* out_y = (float*)d_out;
    float* out_label = out_y + (size_t)B_ * C_ * N_;

    float *gf, *gx0, *gpts, *gxn, *grr, *gkT, *gvT, *gwkv, *gffn;
    cudaGetSymbolAddress((void**)&gf, g_f);
    cudaGetSymbolAddress((void**)&gx0, g_x0);
    cudaGetSymbolAddress((void**)&gpts, g_pts);
    cudaGetSymbolAddress((void**)&gxn, g_xn);
    cudaGetSymbolAddress((void**)&grr, g_rr);
    cudaGetSymbolAddress((void**)&gkT, g_kT);
    cudaGetSymbolAddress((void**)&gvT, g_vT);
    cudaGetSymbolAddress((void**)&gwkv, g_wkv);
    cudaGetSymbolAddress((void**)&gffn, g_ffn);

    __nv_bfloat16 *wak_h, *wak_l, *wav_h, *wav_l, *war_h, *war_l, *wao_h, *wao_l;
    __nv_bfloat16 *wfk_h, *wfk_l, *wfr_h, *wfr_l, *wfv_h, *wfv_l;
    __nv_bfloat16 *w1_h, *w1_l, *w2_h, *w2_l;
    cudaGetSymbolAddress((void**)&wak_h, g_wak_hi); cudaGetSymbolAddress((void**)&wak_l, g_wak_lo);
    cudaGetSymbolAddress((void**)&wav_h, g_wav_hi); cudaGetSymbolAddress((void**)&wav_l, g_wav_lo);
    cudaGetSymbolAddress((void**)&war_h, g_war_hi); cudaGetSymbolAddress((void**)&war_l, g_war_lo);
    cudaGetSymbolAddress((void**)&wao_h, g_wao_hi); cudaGetSymbolAddress((void**)&wao_l, g_wao_lo);
    cudaGetSymbolAddress((void**)&wfk_h, g_wfk_hi); cudaGetSymbolAddress((void**)&wfk_l, g_wfk_lo);
    cudaGetSymbolAddress((void**)&wfr_h, g_wfr_hi); cudaGetSymbolAddress((void**)&wfr_l, g_wfr_lo);
    cudaGetSymbolAddress((void**)&wfv_h, g_wfv_hi); cudaGetSymbolAddress((void**)&wfv_l, g_wfv_lo);
    cudaGetSymbolAddress((void**)&w1_h, g_wT1_hi);  cudaGetSymbolAddress((void**)&w1_l, g_wT1_lo);
    cudaGetSymbolAddress((void**)&w2_h, g_wT2_hi);  cudaGetSymbolAddress((void**)&w2_l, g_wT2_lo);

    cudaFuncSetAttribute(k_mma_kpconv, cudaFuncAttributeMaxDynamicSharedMemorySize, SM_MMA);
    cudaFuncSetAttribute(k_hgemm, cudaFuncAttributeMaxDynamicSharedMemorySize, H_SZ);

    dim3 tb(32, 8);
    dim3 tgrid(N_ / 32, C_ / 32, B_);

    // 1: setup (kpts + xyz + all weight splits)
    k_setup<<<1617, 256>>>(p, kp1_w, kp2_w, att_wk, att_wv, att_wr, att_wo,
                           ffn_wk, ffn_wr, ffn_wv);
    // 2: knn + feature transpose
    k_knn_prep<<<2048, 256>>>(x);
    // 3: build fk(f0)
    k_build_fk<<<M_ / 2, 128>>>(gf);
    // 4: KPConv 1 GEMM (profiled)
    k_mma_kpconv<<<M_ / 64, 256, SM_MMA>>>(w1_h, w1_l, gf, nullptr, gf);
    // 5-6: KPConv 2
    k_build_fk<<<M_ / 2, 128>>>(gf);
    k_mma_kpconv<<<M_ / 64, 256, SM_MMA>>>(w2_h, w2_l, gf, gx0, gpts);

    // ---- RWKV spatial mix ----
    k_ln<<<M_, 128>>>(gpts, ln1_g, ln1_b, gxn);
    k_hgemm<<<dim3(128, 2), 256, H_SZ>>>(gxn, wak_h, wak_l, gkT, nullptr, nullptr, mix_k, C_, C_, 0, 1);
    k_hgemm<<<dim3(128, 2), 256, H_SZ>>>(gxn, wav_h, wav_l, gvT, nullptr, nullptr, mix_v, C_, C_, 0, 1);
    k_hgemm<<<dim3(128, 2), 256, H_SZ>>>(gxn, war_h, war_l, grr, nullptr, nullptr, mix_r, C_, C_, 1, 0);
    k_wkv<<<32, 256>>>(gkT, gvT, grr, tdcy, tfst, gwkv);
    k_hgemm<<<dim3(128, 2), 256, H_SZ>>>(gwkv, wao_h, wao_l, gpts, gpts, nullptr, nullptr, C_, C_, 0, 0);

    // ---- channel mix ----
    k_ln<<<M_, 128>>>(gpts, ln2_g, ln2_b, gxn);
    k_hgemm<<<dim3(128, 8), 256, H_SZ>>>(gxn, wfk_h, wfk_l, gffn, nullptr, nullptr, cmix_k, C_, F_, 2, 0);
    k_hgemm<<<dim3(128, 2), 256, H_SZ>>>(gxn, wfr_h, wfr_l, grr, nullptr, nullptr, cmix_r, C_, C_, 1, 0);
    k_hgemm<<<dim3(128, 2), 256, H_SZ>>>(gffn, wfv_h, wfv_l, gpts, gpts, grr, nullptr, F_, C_, 0, 0);

    // ---- outputs ----
    k_transpose<<<tgrid, tb>>>(gpts, out_y);
    k_bnpart<<<256, 128>>>(gpts);
    k_bnred<<<1, 128>>>(bn_g, bn_b);
    k_head<<<M_ / 8, 256>>>(gpts, conv_w, conv_b, out_label);
    (void)in_sizes; (void)n_in; (void)out_size;
}